// round 2
// baseline (speedup 1.0000x reference)
#include <cuda_runtime.h>
#include <math.h>

#define B_ROWS   8192
#define M_DIM    512
#define N_DIM    2048
#define IN_COLS  4608   // M + 2N
#define OUT_COLS 8704   // IN_COLS + 2N
#define THETA    0.1f
#define KTH      103    // 103rd largest == sorted_asc[1945] == percentile(95, 'nearest') for n=2048

// Scratch (allocation-guard-safe device globals)
__device__ float g_gx [B_ROWS * N_DIM];
__device__ float g_res[B_ROWS * M_DIM];
__device__ float g_zk [B_ROWS * N_DIM];

// ---------------------------------------------------------------------------
// Kernel 1: passthrough copy of inputs into out[:, :4608] and gx = (1 + 0.5*exp(-|xk|)) * xk
// ---------------------------------------------------------------------------
__global__ void k_copy_gx(const float* __restrict__ in, float* __restrict__ out) {
    int b   = blockIdx.x;
    int tid = threadIdx.x;
    const float4* src = (const float4*)(in  + (size_t)b * IN_COLS);
    float4*       dst = (float4*)(out + (size_t)b * OUT_COLS);
    #pragma unroll 2
    for (int i = tid; i < IN_COLS / 4; i += 256) dst[i] = src[i];

    const float4* xk  = (const float4*)(in + (size_t)b * IN_COLS + 2560);
    float4*       gxr = (float4*)(g_gx + (size_t)b * N_DIM);
    #pragma unroll 2
    for (int i = tid; i < N_DIM / 4; i += 256) {
        float4 v = xk[i];
        float4 g;
        g.x = (1.0f + 0.5f * expf(-fabsf(v.x))) * v.x;
        g.y = (1.0f + 0.5f * expf(-fabsf(v.y))) * v.y;
        g.z = (1.0f + 0.5f * expf(-fabsf(v.z))) * v.z;
        g.w = (1.0f + 0.5f * expf(-fabsf(v.w))) * v.w;
        gxr[i] = g;
    }
}

// ---------------------------------------------------------------------------
// SGEMM tiling parameters: 128x128 block tile, BK=16, 256 threads, 8x8 per thread
// ---------------------------------------------------------------------------
#define BM 128
#define BN 128
#define BK 16
#define TM 8
#define TN 8

// GEMM1: res[b][m] = y[b][m] - sum_k gx[b][k] * A[m][k]      (K = 2048)
// Both operands are K-contiguous in global memory.
__global__ __launch_bounds__(256, 2)
void k_gemm1(const float* __restrict__ Amat, const float* __restrict__ in) {
    __shared__ float As[BK][BM];
    __shared__ float Bs[BK][BN];
    int tid  = threadIdx.x;
    int row0 = blockIdx.y * BM;   // batch rows
    int col0 = blockIdx.x * BN;   // output features (rows of A)
    int tx = tid % 16, ty = tid / 16;
    int lr = tid / 4;             // 0..63 (two rows: lr, lr+64)
    int lc = (tid % 4) * 4;       // 0,4,8,12

    float acc[TM][TN] = {};

    for (int k0 = 0; k0 < N_DIM; k0 += BK) {
        #pragma unroll
        for (int rr = 0; rr < 2; rr++) {
            int r = lr + rr * 64;
            float4 v = *(const float4*)(g_gx + (size_t)(row0 + r) * N_DIM + k0 + lc);
            As[lc + 0][r] = v.x; As[lc + 1][r] = v.y; As[lc + 2][r] = v.z; As[lc + 3][r] = v.w;
        }
        #pragma unroll
        for (int rr = 0; rr < 2; rr++) {
            int n = lr + rr * 64;
            float4 v = *(const float4*)(Amat + (size_t)(col0 + n) * N_DIM + k0 + lc);
            Bs[lc + 0][n] = v.x; Bs[lc + 1][n] = v.y; Bs[lc + 2][n] = v.z; Bs[lc + 3][n] = v.w;
        }
        __syncthreads();
        #pragma unroll
        for (int k = 0; k < BK; k++) {
            float ra[TM], rb[TN];
            #pragma unroll
            for (int i = 0; i < TM; i++) ra[i] = As[k][ty * TM + i];
            #pragma unroll
            for (int j = 0; j < TN; j++) rb[j] = Bs[k][tx * TN + j];
            #pragma unroll
            for (int i = 0; i < TM; i++)
                #pragma unroll
                for (int j = 0; j < TN; j++)
                    acc[i][j] += ra[i] * rb[j];
        }
        __syncthreads();
    }
    // epilogue: res = y - acc   (y = inputs[:, :512])
    #pragma unroll
    for (int i = 0; i < TM; i++) {
        int r = row0 + ty * TM + i;
        #pragma unroll
        for (int j = 0; j < TN; j++) {
            int c = col0 + tx * TN + j;
            g_res[(size_t)r * M_DIM + c] = in[(size_t)r * IN_COLS + c] - acc[i][j];
        }
    }
}

// GEMM2: zk[b][n] = gx[b][n] + 0.9 * sum_k res[b][k] * W[k][n]   (K = 512)
__global__ __launch_bounds__(256, 2)
void k_gemm2(const float* __restrict__ Wmat) {
    __shared__ float As[BK][BM];
    __shared__ float Bs[BK][BN];
    int tid  = threadIdx.x;
    int row0 = blockIdx.y * BM;
    int col0 = blockIdx.x * BN;
    int tx = tid % 16, ty = tid / 16;
    int lr = tid / 4;
    int lc = (tid % 4) * 4;
    int bk = tid / 32;            // 0..7 (two k's: bk, bk+8)
    int bn = (tid % 32) * 4;      // 0..124

    float acc[TM][TN] = {};

    for (int k0 = 0; k0 < M_DIM; k0 += BK) {
        #pragma unroll
        for (int rr = 0; rr < 2; rr++) {
            int r = lr + rr * 64;
            float4 v = *(const float4*)(g_res + (size_t)(row0 + r) * M_DIM + k0 + lc);
            As[lc + 0][r] = v.x; As[lc + 1][r] = v.y; As[lc + 2][r] = v.z; As[lc + 3][r] = v.w;
        }
        #pragma unroll
        for (int rr = 0; rr < 2; rr++) {
            int k = bk + rr * 8;
            *(float4*)&Bs[k][bn] =
                *(const float4*)(Wmat + (size_t)(k0 + k) * N_DIM + col0 + bn);
        }
        __syncthreads();
        #pragma unroll
        for (int k = 0; k < BK; k++) {
            float ra[TM], rb[TN];
            #pragma unroll
            for (int i = 0; i < TM; i++) ra[i] = As[k][ty * TM + i];
            #pragma unroll
            for (int j = 0; j < TN; j++) rb[j] = Bs[k][tx * TN + j];
            #pragma unroll
            for (int i = 0; i < TM; i++)
                #pragma unroll
                for (int j = 0; j < TN; j++)
                    acc[i][j] += ra[i] * rb[j];
        }
        __syncthreads();
    }
    #pragma unroll
    for (int i = 0; i < TM; i++) {
        int r = row0 + ty * TM + i;
        #pragma unroll
        for (int j = 0; j < TN; j++) {
            int c = col0 + tx * TN + j;
            size_t idx = (size_t)r * N_DIM + c;
            g_zk[idx] = g_gx[idx] + 0.9f * acc[i][j];
        }
    }
}

// ---------------------------------------------------------------------------
// Kernel 4: per-row exact k-th largest (bitwise radix select on |zk| bit
// patterns, register-resident) + shrink_ss + gating; writes cindex & output.
// ---------------------------------------------------------------------------
__global__ void k_shrink(const float* __restrict__ in, float* __restrict__ out) {
    int b   = blockIdx.x;
    int tid = threadIdx.x;
    __shared__ int scnt;

    const float* z = g_zk + (size_t)b * N_DIM;
    float    zf[8];
    unsigned vb[8];
    #pragma unroll
    for (int q = 0; q < 8; q++) {
        zf[q] = z[tid + q * 256];
        vb[q] = __float_as_uint(fabsf(zf[q]));
    }

    // k-th largest via MSB-down bitwise radix select (|z| >= 0, bit 31 == 0)
    unsigned prefix = 0u;
    int k = KTH;
    for (int bit = 30; bit >= 0; --bit) {
        if (tid == 0) scnt = 0;
        __syncthreads();
        unsigned mask = ~((1u << bit) - 1u);
        unsigned cand = prefix | (1u << bit);
        int c = 0;
        #pragma unroll
        for (int q = 0; q < 8; q++) c += ((vb[q] & mask) == cand);
        #pragma unroll
        for (int off = 16; off > 0; off >>= 1) c += __shfl_down_sync(0xffffffffu, c, off);
        if ((tid & 31) == 0 && c) atomicAdd(&scnt, c);
        __syncthreads();
        int cnt = scnt;
        if (cnt >= k) prefix = cand; else k -= cnt;
        __syncthreads();
    }
    float thres = __uint_as_float(prefix);

    const float* row_in = in + (size_t)b * IN_COLS;
    float* crow = out + (size_t)b * OUT_COLS + IN_COLS;          // cindex
    float* orow = crow + N_DIM;                                  // output

    #pragma unroll
    for (int q = 0; q < 8; q++) {
        int   i   = tid + q * 256;
        float zv  = zf[q];
        float az  = __uint_as_float(vb[q]);
        float ind = (az > THETA && az > thres) ? 1.0f : 0.0f;
        float ci  = 1.0f - ind;
        float soft = copysignf(fmaxf(az * ci - THETA, 0.0f), zv);
        float xt   = ind * zv + soft;
        float xkv  = row_in[2560 + i];
        float cprv = row_in[512 + i];
        float p1   = 1.0f / (fabsf(xt - xkv) + 0.1f);
        float g    = 1.0f - 0.5f * p1 * (THETA * cprv);
        float ov   = g * xt + (1.0f - g) * xkv;
        crow[i] = ci;
        orow[i] = ov;
    }
}

// ---------------------------------------------------------------------------
extern "C" void kernel_launch(void* const* d_in, const int* in_sizes, int n_in,
                              void* d_out, int out_size) {
    (void)in_sizes; (void)n_in; (void)out_size;
    const float* in = (const float*)d_in[0];   // (8192, 4608)
    const float* A  = (const float*)d_in[1];   // (512, 2048)
    const float* W  = (const float*)d_in[2];   // (512, 2048)
    float* out = (float*)d_out;                // (8192, 8704)

    k_copy_gx<<<B_ROWS, 256>>>(in, out);
    k_gemm1<<<dim3(M_DIM / BN, B_ROWS / BM), 256>>>(A, in);
    k_gemm2<<<dim3(N_DIM / BN, B_ROWS / BM), 256>>>(W);
    k_shrink<<<B_ROWS, 256>>>(in, out);
}

// round 4
// speedup vs baseline: 1.9181x; 1.9181x over previous
#include <cuda_runtime.h>
#include <cuda_bf16.h>
#include <math.h>
#include <stdint.h>

#define B_ROWS   8192
#define M_DIM    512
#define N_DIM    2048
#define IN_COLS  4608
#define OUT_COLS 8704
#define THETA    0.1f
#define KTH      103

// ---- scratch: planar bf16 hi/lo operands -----------------------------------
__device__ __align__(16) unsigned char g_gxh [33554432]; // 8192x2048 bf16
__device__ __align__(16) unsigned char g_gxl [33554432];
__device__ __align__(16) unsigned char g_Ah  [2097152];  // 512x2048
__device__ __align__(16) unsigned char g_Al  [2097152];
__device__ __align__(16) unsigned char g_Wth [2097152];  // Wt: 2048x512
__device__ __align__(16) unsigned char g_Wtl [2097152];
__device__ __align__(16) unsigned char g_resh[8388608];  // 8192x512
__device__ __align__(16) unsigned char g_resl[8388608];
__device__ float g_zk[(size_t)B_ROWS * N_DIM];

// ---- helpers ----------------------------------------------------------------
__device__ __forceinline__ uint32_t smem_u32(const void* p) {
    uint32_t a;
    asm("{ .reg .u64 t; cvta.to.shared.u64 t, %1; cvt.u32.u64 %0, t; }" : "=r"(a) : "l"(p));
    return a;
}
__device__ __forceinline__ void cpa(uint32_t dst, const void* src) {
    asm volatile("cp.async.cg.shared.global [%0], [%1], 16;" :: "r"(dst), "l"(src));
}
__device__ __forceinline__ void ldsm4(uint32_t* r, uint32_t a) {
    asm volatile("ldmatrix.sync.aligned.m8n8.x4.shared.b16 {%0,%1,%2,%3}, [%4];"
                 : "=r"(r[0]), "=r"(r[1]), "=r"(r[2]), "=r"(r[3]) : "r"(a));
}
__device__ __forceinline__ void mma16816(float* c, const uint32_t* a, const uint32_t* b) {
    asm volatile(
        "mma.sync.aligned.m16n8k16.row.col.f32.bf16.bf16.f32 "
        "{%0,%1,%2,%3}, {%4,%5,%6,%7}, {%8,%9}, {%0,%1,%2,%3};"
        : "+f"(c[0]), "+f"(c[1]), "+f"(c[2]), "+f"(c[3])
        : "r"(a[0]), "r"(a[1]), "r"(a[2]), "r"(a[3]), "r"(b[0]), "r"(b[1]));
}
union U16x8 { unsigned short s[8]; uint4 v; };
union U16x4 { unsigned short s[4]; uint2 v; };
__device__ __forceinline__ void bsplit(float x, unsigned short& h, unsigned short& l) {
    __nv_bfloat16 bh = __float2bfloat16(x);
    __nv_bfloat16 bl = __float2bfloat16(x - __bfloat162float(bh));
    h = __bfloat16_as_ushort(bh); l = __bfloat16_as_ushort(bl);
}

// ---- prep kernels -------------------------------------------------------------
__global__ void k_copy_gx(const float* __restrict__ in, float* __restrict__ out) {
    int b = blockIdx.x, tid = threadIdx.x;
    const float4* src = (const float4*)(in + (size_t)b * IN_COLS);
    float4* dst = (float4*)(out + (size_t)b * OUT_COLS);
    #pragma unroll 2
    for (int i = tid; i < IN_COLS / 4; i += 256) dst[i] = src[i];

    int c0 = tid * 8;
    const float4* xs = (const float4*)(in + (size_t)b * IN_COLS + 2560 + c0);
    float4 v0 = xs[0], v1 = xs[1];
    float x[8] = {v0.x, v0.y, v0.z, v0.w, v1.x, v1.y, v1.z, v1.w};
    U16x8 ph, pl;
    #pragma unroll
    for (int e = 0; e < 8; e++) {
        float g = (1.0f + 0.5f * expf(-fabsf(x[e]))) * x[e];
        bsplit(g, ph.s[e], pl.s[e]);
    }
    size_t o = ((size_t)b * N_DIM + c0) * 2;
    *(uint4*)(g_gxh + o) = ph.v;
    *(uint4*)(g_gxl + o) = pl.v;
}

__global__ void k_prep_A(const float* __restrict__ A) {
    int n = blockIdx.x, tid = threadIdx.x, c0 = tid * 8;
    const float4* xs = (const float4*)(A + (size_t)n * N_DIM + c0);
    float4 v0 = xs[0], v1 = xs[1];
    float x[8] = {v0.x, v0.y, v0.z, v0.w, v1.x, v1.y, v1.z, v1.w};
    U16x8 ph, pl;
    #pragma unroll
    for (int e = 0; e < 8; e++) bsplit(x[e], ph.s[e], pl.s[e]);
    size_t o = ((size_t)n * N_DIM + c0) * 2;
    *(uint4*)(g_Ah + o) = ph.v;
    *(uint4*)(g_Al + o) = pl.v;
}

__global__ void k_prep_W(const float* __restrict__ W) {  // Wt[n][k] = W[k][n]
    __shared__ float ts[32][33];
    int n0 = blockIdx.x * 32, k0 = blockIdx.y * 32, tid = threadIdx.x;
    #pragma unroll
    for (int i = 0; i < 4; i++) {
        int idx = tid + i * 256, kl = idx >> 5, nl = idx & 31;
        ts[kl][nl] = W[(size_t)(k0 + kl) * N_DIM + n0 + nl];
    }
    __syncthreads();
    int nl = tid >> 3, kq = (tid & 7) * 4;
    U16x4 ph, pl;
    #pragma unroll
    for (int j = 0; j < 4; j++) bsplit(ts[kq + j][nl], ph.s[j], pl.s[j]);
    size_t o = ((size_t)(n0 + nl) * M_DIM + k0 + kq) * 2;
    *(uint2*)(g_Wth + o) = ph.v;
    *(uint2*)(g_Wtl + o) = pl.v;
}

// ---- mma.sync GEMM core --------------------------------------------------------
// smem stage (40960B): Ah[128][40] | Al | Bh | Bl  (80B row pitch; 3 stages)
#define STAGE_BYTES 40960
#define GEMM_SMEM   (3 * STAGE_BYTES)

__device__ __forceinline__ void stage_load(
    uint32_t sbase, int s, int c,
    const unsigned char* Ah, const unsigned char* Al,
    const unsigned char* Bh, const unsigned char* Bl,
    int bm, int bn, int KLD, int tid)
{
    uint32_t sb = sbase + s * STAGE_BYTES;
    int r = tid >> 2, seg = tid & 3;
    size_t kb = ((size_t)c * 32 + seg * 8) * 2;
    #pragma unroll
    for (int p = 0; p < 2; p++) {
        int row = r + p * 64;
        size_t ga = (size_t)(bm + row) * KLD * 2 + kb;
        size_t gb = (size_t)(bn + row) * KLD * 2 + kb;
        uint32_t so = (uint32_t)row * 80 + seg * 16;
        cpa(sb + so,         Ah + ga);
        cpa(sb + 10240 + so, Al + ga);
        cpa(sb + 20480 + so, Bh + gb);
        cpa(sb + 30720 + so, Bl + gb);
    }
    asm volatile("cp.async.commit_group;" ::: "memory");
}

template<int NCHUNK, int KLD>
__device__ __forceinline__ void mma_mainloop(
    uint32_t sbase,
    const unsigned char* Ah, const unsigned char* Al,
    const unsigned char* Bh, const unsigned char* Bl,
    int bm, int bn, float acc[2][8][4])
{
    int tid = threadIdx.x, lane = tid & 31, wid = tid >> 5;
    int m0 = (wid & 3) * 32, n0 = (wid >> 2) * 64;

    stage_load(sbase, 0, 0, Ah, Al, Bh, Bl, bm, bn, KLD, tid);
    stage_load(sbase, 1, 1, Ah, Al, Bh, Bl, bm, bn, KLD, tid);

    // precomputed intra-stage ldmatrix offsets
    uint32_t a_off = (uint32_t)(m0 + (lane & 15)) * 80 + (lane >> 4) * 16;
    uint32_t b_off = (uint32_t)(n0 + (lane & 7) + ((lane >> 4) & 1) * 8) * 80
                   + ((lane >> 3) & 1) * 16;

    for (int c = 0; c < NCHUNK; c++) {
        asm volatile("cp.async.wait_group 1;" ::: "memory");
        __syncthreads();
        int s = c % 3;
        if (c + 2 < NCHUNK)
            stage_load(sbase, (c + 2) % 3, c + 2, Ah, Al, Bh, Bl, bm, bn, KLD, tid);
        else
            asm volatile("cp.async.commit_group;" ::: "memory");

        uint32_t sb = sbase + s * STAGE_BYTES;
        #pragma unroll
        for (int ks = 0; ks < 2; ks++) {
            uint32_t ah[2][4], al[2][4], bh[8][2], bl[8][2];
            #pragma unroll
            for (int i = 0; i < 2; i++) {
                uint32_t ad = sb + a_off + i * (16 * 80) + ks * 32;
                ldsm4(ah[i], ad);
                ldsm4(al[i], ad + 10240);
            }
            #pragma unroll
            for (int j2 = 0; j2 < 4; j2++) {
                uint32_t bd = sb + 20480 + b_off + j2 * (16 * 80) + ks * 32;
                uint32_t t[4];
                ldsm4(t, bd);
                bh[2*j2][0] = t[0]; bh[2*j2][1] = t[1];
                bh[2*j2+1][0] = t[2]; bh[2*j2+1][1] = t[3];
                ldsm4(t, bd + 10240);
                bl[2*j2][0] = t[0]; bl[2*j2][1] = t[1];
                bl[2*j2+1][0] = t[2]; bl[2*j2+1][1] = t[3];
            }
            #pragma unroll
            for (int i = 0; i < 2; i++)
                #pragma unroll
                for (int j = 0; j < 8; j++) {
                    mma16816(acc[i][j], ah[i], bh[j]);
                    mma16816(acc[i][j], ah[i], bl[j]);
                    mma16816(acc[i][j], al[i], bh[j]);
                    mma16816(acc[i][j], al[i], bl[j]);
                }
        }
    }
}

// GEMM1: res = y - gx @ A^T ; writes res split bf16 hi/lo [8192,512]
__global__ __launch_bounds__(256, 1) void k_gemm1_mma(const float* __restrict__ in) {
    extern __shared__ unsigned char sm[];
    uint32_t sbase = smem_u32(sm);
    int bm = blockIdx.y * 128, bn = blockIdx.x * 128;
    float acc[2][8][4] = {};
    mma_mainloop<64, N_DIM>(sbase, g_gxh, g_gxl, g_Ah, g_Al, bm, bn, acc);

    int lane = threadIdx.x & 31, wid = threadIdx.x >> 5;
    int m0 = (wid & 3) * 32, n0 = (wid >> 2) * 64;
    #pragma unroll
    for (int i = 0; i < 2; i++) {
        int rb = bm + m0 + 16 * i + (lane >> 2);
        #pragma unroll
        for (int j = 0; j < 8; j++) {
            int col = bn + n0 + 8 * j + (lane & 3) * 2;
            #pragma unroll
            for (int h = 0; h < 2; h++) {
                int row = rb + 8 * h;
                float2 y = *(const float2*)(in + (size_t)row * IN_COLS + col);
                unsigned short h0, l0, h1, l1;
                bsplit(y.x - acc[i][j][2*h + 0], h0, l0);
                bsplit(y.y - acc[i][j][2*h + 1], h1, l1);
                size_t o = ((size_t)row * M_DIM + col) * 2;
                *(uint32_t*)(g_resh + o) = (uint32_t)h0 | ((uint32_t)h1 << 16);
                *(uint32_t*)(g_resl + o) = (uint32_t)l0 | ((uint32_t)l1 << 16);
            }
        }
    }
}

// GEMM2: zk = gx + 0.9 * res @ W ; writes zk fp32 [8192,2048]
__global__ __launch_bounds__(256, 1) void k_gemm2_mma(const float* __restrict__ in) {
    extern __shared__ unsigned char sm[];
    uint32_t sbase = smem_u32(sm);
    int bm = blockIdx.y * 128, bn = blockIdx.x * 128;
    float acc[2][8][4] = {};
    mma_mainloop<16, M_DIM>(sbase, g_resh, g_resl, g_Wth, g_Wtl, bm, bn, acc);

    int lane = threadIdx.x & 31, wid = threadIdx.x >> 5;
    int m0 = (wid & 3) * 32, n0 = (wid >> 2) * 64;
    #pragma unroll
    for (int i = 0; i < 2; i++) {
        int rb = bm + m0 + 16 * i + (lane >> 2);
        #pragma unroll
        for (int j = 0; j < 8; j++) {
            int col = bn + n0 + 8 * j + (lane & 3) * 2;
            #pragma unroll
            for (int h = 0; h < 2; h++) {
                int row = rb + 8 * h;
                float2 xk = *(const float2*)(in + (size_t)row * IN_COLS + 2560 + col);
                float gx0 = (1.0f + 0.5f * expf(-fabsf(xk.x))) * xk.x;
                float gx1 = (1.0f + 0.5f * expf(-fabsf(xk.y))) * xk.y;
                float2 z;
                z.x = gx0 + 0.9f * acc[i][j][2*h + 0];
                z.y = gx1 + 0.9f * acc[i][j][2*h + 1];
                *(float2*)(g_zk + (size_t)row * N_DIM + col) = z;
            }
        }
    }
}

// ---- shrink: 4-level histogram exact k-th largest + gating ---------------------
__global__ void k_shrink(const float* __restrict__ in, float* __restrict__ out) {
    int b = blockIdx.x, tid = threadIdx.x;
    __shared__ int hist[256];
    __shared__ unsigned s_pfx;
    __shared__ int s_k;

    const float* z = g_zk + (size_t)b * N_DIM;
    float zf[8]; unsigned vb[8];
    #pragma unroll
    for (int q = 0; q < 8; q++) {
        zf[q] = z[tid + q * 256];
        vb[q] = __float_as_uint(fabsf(zf[q]));
    }

    const int SHIFT[4] = {23, 15, 7, 0};
    const int HS[4]    = {31, 23, 15, 7};
    unsigned pfx = 0u; int k = KTH;
    #pragma unroll
    for (int lvl = 0; lvl < 4; lvl++) {
        int sh = SHIFT[lvl], hs = HS[lvl];
        hist[tid] = 0;
        __syncthreads();
        unsigned phi = pfx >> hs;
        #pragma unroll
        for (int q = 0; q < 8; q++)
            if ((vb[q] >> hs) == phi) atomicAdd(&hist[(vb[q] >> sh) & 0xFF], 1);
        __syncthreads();
        if (tid < 32) {
            int base = 255 - tid * 8, c[8], s = 0;
            #pragma unroll
            for (int j = 0; j < 8; j++) { c[j] = hist[base - j]; s += c[j]; }
            int incl = s;
            #pragma unroll
            for (int off = 1; off < 32; off <<= 1) {
                int t = __shfl_up_sync(0xffffffffu, incl, off);
                if (tid >= off) incl += t;
            }
            int excl = incl - s;
            if (excl < k && incl >= k) {
                int kk = k - excl, bin = base;
                #pragma unroll
                for (int j = 0; j < 8; j++) {
                    if (kk <= c[j]) { bin = base - j; break; }
                    kk -= c[j];
                }
                s_pfx = pfx | ((unsigned)bin << sh);
                s_k = kk;
            }
        }
        __syncthreads();
        pfx = s_pfx; k = s_k;
        __syncthreads();
    }
    float thres = __uint_as_float(pfx);

    const float* row_in = in + (size_t)b * IN_COLS;
    float* crow = out + (size_t)b * OUT_COLS + IN_COLS;
    float* orow = crow + N_DIM;
    #pragma unroll
    for (int q = 0; q < 8; q++) {
        int i = tid + q * 256;
        float zv = zf[q], az = __uint_as_float(vb[q]);
        float ind = (az > THETA && az > thres) ? 1.0f : 0.0f;
        float ci = 1.0f - ind;
        float soft = copysignf(fmaxf(az * ci - THETA, 0.0f), zv);
        float xt = ind * zv + soft;
        float xkv = row_in[2560 + i], cprv = row_in[512 + i];
        float p1 = 1.0f / (fabsf(xt - xkv) + 0.1f);
        float g = 1.0f - 0.5f * p1 * (THETA * cprv);
        crow[i] = ci;
        orow[i] = g * xt + (1.0f - g) * xkv;
    }
}

// ----------------------------------------------------------------------------------
extern "C" void kernel_launch(void* const* d_in, const int* in_sizes, int n_in,
                              void* d_out, int out_size) {
    (void)in_sizes; (void)n_in; (void)out_size;
    const float* in = (const float*)d_in[0];
    const float* A  = (const float*)d_in[1];
    const float* W  = (const float*)d_in[2];
    float* out = (float*)d_out;

    static int init = 0;
    if (!init) {
        cudaFuncSetAttribute(k_gemm1_mma, cudaFuncAttributeMaxDynamicSharedMemorySize, GEMM_SMEM);
        cudaFuncSetAttribute(k_gemm2_mma, cudaFuncAttributeMaxDynamicSharedMemorySize, GEMM_SMEM);
        init = 1;
    }

    k_copy_gx<<<B_ROWS, 256>>>(in, out);
    k_prep_A<<<M_DIM, 256>>>(A);
    k_prep_W<<<dim3(N_DIM / 32, M_DIM / 32), 256>>>(W);
    k_gemm1_mma<<<dim3(M_DIM / 128, B_ROWS / 128), 256, GEMM_SMEM>>>(in);
    k_gemm2_mma<<<dim3(N_DIM / 128, B_ROWS / 128), 256, GEMM_SMEM>>>(in);
    k_shrink<<<B_ROWS, 256>>>(in, out);
}

// round 5
// speedup vs baseline: 2.1763x; 1.1346x over previous
#include <cuda_runtime.h>
#include <cuda_bf16.h>
#include <math.h>
#include <stdint.h>

#define B_ROWS   8192
#define M_DIM    512
#define N_DIM    2048
#define IN_COLS  4608
#define OUT_COLS 8704
#define THETA    0.1f
#define KTH      103

// ---- scratch: planar bf16 hi/lo operands -----------------------------------
__device__ __align__(16) unsigned char g_gxh [33554432]; // 8192x2048 bf16
__device__ __align__(16) unsigned char g_gxl [33554432];
__device__ __align__(16) unsigned char g_Ah  [2097152];  // 512x2048
__device__ __align__(16) unsigned char g_Al  [2097152];
__device__ __align__(16) unsigned char g_Wth [2097152];  // Wt: 2048x512
__device__ __align__(16) unsigned char g_Wtl [2097152];
__device__ __align__(16) unsigned char g_resh[8388608];  // 8192x512
__device__ __align__(16) unsigned char g_resl[8388608];
__device__ float g_zk[(size_t)B_ROWS * N_DIM];

// ---- helpers ----------------------------------------------------------------
__device__ __forceinline__ uint32_t smem_u32(const void* p) {
    uint32_t a;
    asm("{ .reg .u64 t; cvta.to.shared.u64 t, %1; cvt.u32.u64 %0, t; }" : "=r"(a) : "l"(p));
    return a;
}
__device__ __forceinline__ void cpa(uint32_t dst, const void* src) {
    asm volatile("cp.async.cg.shared.global [%0], [%1], 16;" :: "r"(dst), "l"(src));
}
__device__ __forceinline__ void ldsm4(uint32_t* r, uint32_t a) {
    asm volatile("ldmatrix.sync.aligned.m8n8.x4.shared.b16 {%0,%1,%2,%3}, [%4];"
                 : "=r"(r[0]), "=r"(r[1]), "=r"(r[2]), "=r"(r[3]) : "r"(a));
}
__device__ __forceinline__ void mma16816(float* c, const uint32_t* a, const uint32_t* b) {
    asm volatile(
        "mma.sync.aligned.m16n8k16.row.col.f32.bf16.bf16.f32 "
        "{%0,%1,%2,%3}, {%4,%5,%6,%7}, {%8,%9}, {%0,%1,%2,%3};"
        : "+f"(c[0]), "+f"(c[1]), "+f"(c[2]), "+f"(c[3])
        : "r"(a[0]), "r"(a[1]), "r"(a[2]), "r"(a[3]), "r"(b[0]), "r"(b[1]));
}
union U16x8 { unsigned short s[8]; uint4 v; };
union U16x4 { unsigned short s[4]; uint2 v; };
__device__ __forceinline__ void bsplit(float x, unsigned short& h, unsigned short& l) {
    __nv_bfloat16 bh = __float2bfloat16(x);
    __nv_bfloat16 bl = __float2bfloat16(x - __bfloat162float(bh));
    h = __bfloat16_as_ushort(bh); l = __bfloat16_as_ushort(bl);
}

// ---- prep kernels -------------------------------------------------------------
__global__ void k_copy_gx(const float* __restrict__ in, float* __restrict__ out) {
    int b = blockIdx.x, tid = threadIdx.x;
    const float4* src = (const float4*)(in + (size_t)b * IN_COLS);
    float4* dst = (float4*)(out + (size_t)b * OUT_COLS);
    #pragma unroll 2
    for (int i = tid; i < IN_COLS / 4; i += 256) dst[i] = src[i];

    int c0 = tid * 8;
    const float4* xs = (const float4*)(in + (size_t)b * IN_COLS + 2560 + c0);
    float4 v0 = xs[0], v1 = xs[1];
    float x[8] = {v0.x, v0.y, v0.z, v0.w, v1.x, v1.y, v1.z, v1.w};
    U16x8 ph, pl;
    #pragma unroll
    for (int e = 0; e < 8; e++) {
        float g = (1.0f + 0.5f * expf(-fabsf(x[e]))) * x[e];
        bsplit(g, ph.s[e], pl.s[e]);
    }
    size_t o = ((size_t)b * N_DIM + c0) * 2;
    *(uint4*)(g_gxh + o) = ph.v;
    *(uint4*)(g_gxl + o) = pl.v;
}

__global__ void k_prep_A(const float* __restrict__ A) {
    int n = blockIdx.x, tid = threadIdx.x, c0 = tid * 8;
    const float4* xs = (const float4*)(A + (size_t)n * N_DIM + c0);
    float4 v0 = xs[0], v1 = xs[1];
    float x[8] = {v0.x, v0.y, v0.z, v0.w, v1.x, v1.y, v1.z, v1.w};
    U16x8 ph, pl;
    #pragma unroll
    for (int e = 0; e < 8; e++) bsplit(x[e], ph.s[e], pl.s[e]);
    size_t o = ((size_t)n * N_DIM + c0) * 2;
    *(uint4*)(g_Ah + o) = ph.v;
    *(uint4*)(g_Al + o) = pl.v;
}

__global__ void k_prep_W(const float* __restrict__ W) {  // Wt[n][k] = W[k][n]
    __shared__ float ts[32][33];
    int n0 = blockIdx.x * 32, k0 = blockIdx.y * 32, tid = threadIdx.x;
    #pragma unroll
    for (int i = 0; i < 4; i++) {
        int idx = tid + i * 256, kl = idx >> 5, nl = idx & 31;
        ts[kl][nl] = W[(size_t)(k0 + kl) * N_DIM + n0 + nl];
    }
    __syncthreads();
    int nl = tid >> 3, kq = (tid & 7) * 4;
    U16x4 ph, pl;
    #pragma unroll
    for (int j = 0; j < 4; j++) bsplit(ts[kq + j][nl], ph.s[j], pl.s[j]);
    size_t o = ((size_t)(n0 + nl) * M_DIM + k0 + kq) * 2;
    *(uint2*)(g_Wth + o) = ph.v;
    *(uint2*)(g_Wtl + o) = pl.v;
}

// ---- mma.sync GEMM core --------------------------------------------------------
// smem stage (40960B): Ah[128][40] | Al | Bh | Bl  (80B row pitch; 3 stages)
#define STAGE_BYTES 40960
#define GEMM_SMEM   (3 * STAGE_BYTES)

__device__ __forceinline__ void stage_load(
    uint32_t sbase, int s, int c,
    const unsigned char* Ah, const unsigned char* Al,
    const unsigned char* Bh, const unsigned char* Bl,
    int bm, int bn, int KLD, int tid)
{
    uint32_t sb = sbase + s * STAGE_BYTES;
    int r = tid >> 2, seg = tid & 3;
    size_t kb = ((size_t)c * 32 + seg * 8) * 2;
    #pragma unroll
    for (int p = 0; p < 2; p++) {
        int row = r + p * 64;
        size_t ga = (size_t)(bm + row) * KLD * 2 + kb;
        size_t gb = (size_t)(bn + row) * KLD * 2 + kb;
        uint32_t so = (uint32_t)row * 80 + seg * 16;
        cpa(sb + so,         Ah + ga);
        cpa(sb + 10240 + so, Al + ga);
        cpa(sb + 20480 + so, Bh + gb);
        cpa(sb + 30720 + so, Bl + gb);
    }
    asm volatile("cp.async.commit_group;" ::: "memory");
}

template<int NCHUNK, int KLD>
__device__ __forceinline__ void mma_mainloop(
    uint32_t sbase,
    const unsigned char* Ah, const unsigned char* Al,
    const unsigned char* Bh, const unsigned char* Bl,
    int bm, int bn, float acc[2][8][4])
{
    int tid = threadIdx.x, lane = tid & 31, wid = tid >> 5;
    int m0 = (wid & 3) * 32, n0 = (wid >> 2) * 64;

    stage_load(sbase, 0, 0, Ah, Al, Bh, Bl, bm, bn, KLD, tid);
    stage_load(sbase, 1, 1, Ah, Al, Bh, Bl, bm, bn, KLD, tid);

    uint32_t a_off = (uint32_t)(m0 + (lane & 15)) * 80 + (lane >> 4) * 16;
    uint32_t b_off = (uint32_t)(n0 + (lane & 7) + ((lane >> 4) & 1) * 8) * 80
                   + ((lane >> 3) & 1) * 16;

    for (int c = 0; c < NCHUNK; c++) {
        asm volatile("cp.async.wait_group 1;" ::: "memory");
        __syncthreads();
        int s = c % 3;
        if (c + 2 < NCHUNK)
            stage_load(sbase, (c + 2) % 3, c + 2, Ah, Al, Bh, Bl, bm, bn, KLD, tid);
        else
            asm volatile("cp.async.commit_group;" ::: "memory");

        uint32_t sb = sbase + s * STAGE_BYTES;
        #pragma unroll
        for (int ks = 0; ks < 2; ks++) {
            uint32_t ah[2][4], al[2][4], bh[8][2], bl[8][2];
            #pragma unroll
            for (int i = 0; i < 2; i++) {
                uint32_t ad = sb + a_off + i * (16 * 80) + ks * 32;
                ldsm4(ah[i], ad);
                ldsm4(al[i], ad + 10240);
            }
            #pragma unroll
            for (int j2 = 0; j2 < 4; j2++) {
                uint32_t bd = sb + 20480 + b_off + j2 * (16 * 80) + ks * 32;
                uint32_t t[4];
                ldsm4(t, bd);
                bh[2*j2][0] = t[0]; bh[2*j2][1] = t[1];
                bh[2*j2+1][0] = t[2]; bh[2*j2+1][1] = t[3];
                ldsm4(t, bd + 10240);
                bl[2*j2][0] = t[0]; bl[2*j2][1] = t[1];
                bl[2*j2+1][0] = t[2]; bl[2*j2+1][1] = t[3];
            }
            // term-major issue order: 16 independent MMAs between accumulator reuse
            #pragma unroll
            for (int i = 0; i < 2; i++)
                #pragma unroll
                for (int j = 0; j < 8; j++)
                    mma16816(acc[i][j], ah[i], bh[j]);
            #pragma unroll
            for (int i = 0; i < 2; i++)
                #pragma unroll
                for (int j = 0; j < 8; j++)
                    mma16816(acc[i][j], ah[i], bl[j]);
            #pragma unroll
            for (int i = 0; i < 2; i++)
                #pragma unroll
                for (int j = 0; j < 8; j++)
                    mma16816(acc[i][j], al[i], bh[j]);
            // ll term dropped: contributes ~2^-16 relative (3-term split)
        }
    }
}

// GEMM1: res = y - gx @ A^T ; writes res split bf16 hi/lo [8192,512]
__global__ __launch_bounds__(256, 1) void k_gemm1_mma(const float* __restrict__ in) {
    extern __shared__ unsigned char sm[];
    uint32_t sbase = smem_u32(sm);
    int bm = blockIdx.y * 128, bn = blockIdx.x * 128;
    float acc[2][8][4] = {};
    mma_mainloop<64, N_DIM>(sbase, g_gxh, g_gxl, g_Ah, g_Al, bm, bn, acc);

    int lane = threadIdx.x & 31, wid = threadIdx.x >> 5;
    int m0 = (wid & 3) * 32, n0 = (wid >> 2) * 64;
    #pragma unroll
    for (int i = 0; i < 2; i++) {
        int rb = bm + m0 + 16 * i + (lane >> 2);
        #pragma unroll
        for (int j = 0; j < 8; j++) {
            int col = bn + n0 + 8 * j + (lane & 3) * 2;
            #pragma unroll
            for (int h = 0; h < 2; h++) {
                int row = rb + 8 * h;
                float2 y = *(const float2*)(in + (size_t)row * IN_COLS + col);
                unsigned short h0, l0, h1, l1;
                bsplit(y.x - acc[i][j][2*h + 0], h0, l0);
                bsplit(y.y - acc[i][j][2*h + 1], h1, l1);
                size_t o = ((size_t)row * M_DIM + col) * 2;
                *(uint32_t*)(g_resh + o) = (uint32_t)h0 | ((uint32_t)h1 << 16);
                *(uint32_t*)(g_resl + o) = (uint32_t)l0 | ((uint32_t)l1 << 16);
            }
        }
    }
}

// GEMM2: zk = gx + 0.9 * res @ W ; writes zk fp32 [8192,2048]
__global__ __launch_bounds__(256, 1) void k_gemm2_mma(const float* __restrict__ in) {
    extern __shared__ unsigned char sm[];
    uint32_t sbase = smem_u32(sm);
    int bm = blockIdx.y * 128, bn = blockIdx.x * 128;
    float acc[2][8][4] = {};
    mma_mainloop<16, M_DIM>(sbase, g_resh, g_resl, g_Wth, g_Wtl, bm, bn, acc);

    int lane = threadIdx.x & 31, wid = threadIdx.x >> 5;
    int m0 = (wid & 3) * 32, n0 = (wid >> 2) * 64;
    #pragma unroll
    for (int i = 0; i < 2; i++) {
        int rb = bm + m0 + 16 * i + (lane >> 2);
        #pragma unroll
        for (int j = 0; j < 8; j++) {
            int col = bn + n0 + 8 * j + (lane & 3) * 2;
            #pragma unroll
            for (int h = 0; h < 2; h++) {
                int row = rb + 8 * h;
                float2 xk = *(const float2*)(in + (size_t)row * IN_COLS + 2560 + col);
                float gx0 = (1.0f + 0.5f * expf(-fabsf(xk.x))) * xk.x;
                float gx1 = (1.0f + 0.5f * expf(-fabsf(xk.y))) * xk.y;
                float2 z;
                z.x = gx0 + 0.9f * acc[i][j][2*h + 0];
                z.y = gx1 + 0.9f * acc[i][j][2*h + 1];
                *(float2*)(g_zk + (size_t)row * N_DIM + col) = z;
            }
        }
    }
}

// ---- shrink: 4-level histogram exact k-th largest + gating ---------------------
__global__ void k_shrink(const float* __restrict__ in, float* __restrict__ out) {
    int b = blockIdx.x, tid = threadIdx.x;
    __shared__ int hist[256];
    __shared__ unsigned s_pfx;
    __shared__ int s_k;

    const float* z = g_zk + (size_t)b * N_DIM;
    float zf[8]; unsigned vb[8];
    #pragma unroll
    for (int q = 0; q < 8; q++) {
        zf[q] = z[tid + q * 256];
        vb[q] = __float_as_uint(fabsf(zf[q]));
    }

    const int SHIFT[4] = {23, 15, 7, 0};
    const int HS[4]    = {31, 23, 15, 7};
    unsigned pfx = 0u; int k = KTH;
    #pragma unroll
    for (int lvl = 0; lvl < 4; lvl++) {
        int sh = SHIFT[lvl], hs = HS[lvl];
        hist[tid] = 0;
        __syncthreads();
        unsigned phi = pfx >> hs;
        #pragma unroll
        for (int q = 0; q < 8; q++)
            if ((vb[q] >> hs) == phi) atomicAdd(&hist[(vb[q] >> sh) & 0xFF], 1);
        __syncthreads();
        if (tid < 32) {
            int base = 255 - tid * 8, c[8], s = 0;
            #pragma unroll
            for (int j = 0; j < 8; j++) { c[j] = hist[base - j]; s += c[j]; }
            int incl = s;
            #pragma unroll
            for (int off = 1; off < 32; off <<= 1) {
                int t = __shfl_up_sync(0xffffffffu, incl, off);
                if (tid >= off) incl += t;
            }
            int excl = incl - s;
            if (excl < k && incl >= k) {
                int kk = k - excl, bin = base;
                #pragma unroll
                for (int j = 0; j < 8; j++) {
                    if (kk <= c[j]) { bin = base - j; break; }
                    kk -= c[j];
                }
                s_pfx = pfx | ((unsigned)bin << sh);
                s_k = kk;
            }
        }
        __syncthreads();
        pfx = s_pfx; k = s_k;
        __syncthreads();
    }
    float thres = __uint_as_float(pfx);

    const float* row_in = in + (size_t)b * IN_COLS;
    float* crow = out + (size_t)b * OUT_COLS + IN_COLS;
    float* orow = crow + N_DIM;
    #pragma unroll
    for (int q = 0; q < 8; q++) {
        int i = tid + q * 256;
        float zv = zf[q], az = __uint_as_float(vb[q]);
        float ind = (az > THETA && az > thres) ? 1.0f : 0.0f;
        float ci = 1.0f - ind;
        float soft = copysignf(fmaxf(az * ci - THETA, 0.0f), zv);
        float xt = ind * zv + soft;
        float xkv = row_in[2560 + i], cprv = row_in[512 + i];
        float p1 = 1.0f / (fabsf(xt - xkv) + 0.1f);
        float g = 1.0f - 0.5f * p1 * (THETA * cprv);
        crow[i] = ci;
        orow[i] = g * xt + (1.0f - g) * xkv;
    }
}

// ----------------------------------------------------------------------------------
extern "C" void kernel_launch(void* const* d_in, const int* in_sizes, int n_in,
                              void* d_out, int out_size) {
    (void)in_sizes; (void)n_in; (void)out_size;
    const float* in = (const float*)d_in[0];
    const float* A  = (const float*)d_in[1];
    const float* W  = (const float*)d_in[2];
    float* out = (float*)d_out;

    static int init = 0;
    if (!init) {
        cudaFuncSetAttribute(k_gemm1_mma, cudaFuncAttributeMaxDynamicSharedMemorySize, GEMM_SMEM);
        cudaFuncSetAttribute(k_gemm2_mma, cudaFuncAttributeMaxDynamicSharedMemorySize, GEMM_SMEM);
        init = 1;
    }

    k_copy_gx<<<B_ROWS, 256>>>(in, out);
    k_prep_A<<<M_DIM, 256>>>(A);
    k_prep_W<<<dim3(N_DIM / 32, M_DIM / 32), 256>>>(W);
    k_gemm1_mma<<<dim3(M_DIM / 128, B_ROWS / 128), 256, GEMM_SMEM>>>(in);
    k_gemm2_mma<<<dim3(N_DIM / 128, B_ROWS / 128), 256, GEMM_SMEM>>>(in);
    k_shrink<<<B_ROWS, 256>>>(in, out);
}

// round 6
// speedup vs baseline: 2.3343x; 1.0726x over previous
#include <cuda_runtime.h>
#include <cuda_bf16.h>
#include <math.h>
#include <stdint.h>

#define B_ROWS   8192
#define M_DIM    512
#define N_DIM    2048
#define IN_COLS  4608
#define OUT_COLS 8704
#define THETA    0.1f
#define KTH      103

// ---- scratch: planar bf16 hi/lo operands -----------------------------------
__device__ __align__(16) unsigned char g_gxh [33554432]; // 8192x2048 bf16
__device__ __align__(16) unsigned char g_gxl [33554432];
__device__ __align__(16) unsigned char g_Ah  [2097152];  // 512x2048
__device__ __align__(16) unsigned char g_Al  [2097152];
__device__ __align__(16) unsigned char g_Wth [2097152];  // Wt: 2048x512
__device__ __align__(16) unsigned char g_Wtl [2097152];
__device__ __align__(16) unsigned char g_resh[8388608];  // 8192x512
__device__ __align__(16) unsigned char g_resl[8388608];
__device__ float g_zk[(size_t)B_ROWS * N_DIM];

// ---- helpers ----------------------------------------------------------------
__device__ __forceinline__ uint32_t smem_u32(const void* p) {
    uint32_t a;
    asm("{ .reg .u64 t; cvta.to.shared.u64 t, %1; cvt.u32.u64 %0, t; }" : "=r"(a) : "l"(p));
    return a;
}
__device__ __forceinline__ void cpa(uint32_t dst, const void* src) {
    asm volatile("cp.async.cg.shared.global [%0], [%1], 16;" :: "r"(dst), "l"(src));
}
__device__ __forceinline__ void ldsm4(uint32_t* r, uint32_t a) {
    asm volatile("ldmatrix.sync.aligned.m8n8.x4.shared.b16 {%0,%1,%2,%3}, [%4];"
                 : "=r"(r[0]), "=r"(r[1]), "=r"(r[2]), "=r"(r[3]) : "r"(a));
}
__device__ __forceinline__ void mma16816(float* c, const uint32_t* a, const uint32_t* b) {
    asm volatile(
        "mma.sync.aligned.m16n8k16.row.col.f32.bf16.bf16.f32 "
        "{%0,%1,%2,%3}, {%4,%5,%6,%7}, {%8,%9}, {%0,%1,%2,%3};"
        : "+f"(c[0]), "+f"(c[1]), "+f"(c[2]), "+f"(c[3])
        : "r"(a[0]), "r"(a[1]), "r"(a[2]), "r"(a[3]), "r"(b[0]), "r"(b[1]));
}
union U16x8 { unsigned short s[8]; uint4 v; };
union U16x4 { unsigned short s[4]; uint2 v; };
__device__ __forceinline__ void bsplit(float x, unsigned short& h, unsigned short& l) {
    __nv_bfloat16 bh = __float2bfloat16(x);
    __nv_bfloat16 bl = __float2bfloat16(x - __bfloat162float(bh));
    h = __bfloat16_as_ushort(bh); l = __bfloat16_as_ushort(bl);
}

// ---- prep kernels -------------------------------------------------------------
__global__ void k_copy_gx(const float* __restrict__ in, float* __restrict__ out) {
    int b = blockIdx.x, tid = threadIdx.x;
    const float4* src = (const float4*)(in + (size_t)b * IN_COLS);
    float4* dst = (float4*)(out + (size_t)b * OUT_COLS);
    #pragma unroll 2
    for (int i = tid; i < IN_COLS / 4; i += 256) dst[i] = src[i];

    int c0 = tid * 8;
    const float4* xs = (const float4*)(in + (size_t)b * IN_COLS + 2560 + c0);
    float4 v0 = xs[0], v1 = xs[1];
    float x[8] = {v0.x, v0.y, v0.z, v0.w, v1.x, v1.y, v1.z, v1.w};
    U16x8 ph, pl;
    #pragma unroll
    for (int e = 0; e < 8; e++) {
        float g = (1.0f + 0.5f * expf(-fabsf(x[e]))) * x[e];
        bsplit(g, ph.s[e], pl.s[e]);
    }
    size_t o = ((size_t)b * N_DIM + c0) * 2;
    *(uint4*)(g_gxh + o) = ph.v;
    *(uint4*)(g_gxl + o) = pl.v;
}

__global__ void k_prep_A(const float* __restrict__ A) {
    int n = blockIdx.x, tid = threadIdx.x, c0 = tid * 8;
    const float4* xs = (const float4*)(A + (size_t)n * N_DIM + c0);
    float4 v0 = xs[0], v1 = xs[1];
    float x[8] = {v0.x, v0.y, v0.z, v0.w, v1.x, v1.y, v1.z, v1.w};
    U16x8 ph, pl;
    #pragma unroll
    for (int e = 0; e < 8; e++) bsplit(x[e], ph.s[e], pl.s[e]);
    size_t o = ((size_t)n * N_DIM + c0) * 2;
    *(uint4*)(g_Ah + o) = ph.v;
    *(uint4*)(g_Al + o) = pl.v;
}

__global__ void k_prep_W(const float* __restrict__ W) {  // Wt[n][k] = W[k][n]
    __shared__ float ts[32][33];
    int n0 = blockIdx.x * 32, k0 = blockIdx.y * 32, tid = threadIdx.x;
    #pragma unroll
    for (int i = 0; i < 4; i++) {
        int idx = tid + i * 256, kl = idx >> 5, nl = idx & 31;
        ts[kl][nl] = W[(size_t)(k0 + kl) * N_DIM + n0 + nl];
    }
    __syncthreads();
    int nl = tid >> 3, kq = (tid & 7) * 4;
    U16x4 ph, pl;
    #pragma unroll
    for (int j = 0; j < 4; j++) bsplit(ts[kq + j][nl], ph.s[j], pl.s[j]);
    size_t o = ((size_t)(n0 + nl) * M_DIM + k0 + kq) * 2;
    *(uint2*)(g_Wth + o) = ph.v;
    *(uint2*)(g_Wtl + o) = pl.v;
}

// ---- mma.sync GEMM core ---------------------------------------------------------
// CTA tile 128(m) x 256(n), 512 threads, warp tile 32x64 (4m x 4n warp grid).
// Stage (61440B): Ah[128][40] | Al[128][40] | Bh[256][40] | Bl[256][40], 80B pitch.
#define STAGE_BYTES 61440
#define GEMM_SMEM   (3 * STAGE_BYTES)

__device__ __forceinline__ void stage_load(
    uint32_t sbase, int s, int c,
    const unsigned char* Ah, const unsigned char* Al,
    const unsigned char* Bh, const unsigned char* Bl,
    int bm, int bn, int KLD, int tid)
{
    uint32_t sb = sbase + s * STAGE_BYTES;
    int r = tid >> 2, seg = tid & 3;          // r: 0..127
    size_t kb = ((size_t)c * 32 + seg * 8) * 2;
    uint32_t so = (uint32_t)r * 80 + seg * 16;
    size_t ga = (size_t)(bm + r) * KLD * 2 + kb;
    cpa(sb + so,         Ah + ga);
    cpa(sb + 10240 + so, Al + ga);
    #pragma unroll
    for (int p = 0; p < 2; p++) {
        int row = r + p * 128;
        size_t gb = (size_t)(bn + row) * KLD * 2 + kb;
        uint32_t sob = (uint32_t)row * 80 + seg * 16;
        cpa(sb + 20480 + sob, Bh + gb);
        cpa(sb + 40960 + sob, Bl + gb);
    }
    asm volatile("cp.async.commit_group;" ::: "memory");
}

template<int NCHUNK, int KLD>
__device__ __forceinline__ void mma_mainloop(
    uint32_t sbase,
    const unsigned char* Ah, const unsigned char* Al,
    const unsigned char* Bh, const unsigned char* Bl,
    int bm, int bn, float acc[2][8][4])
{
    int tid = threadIdx.x, lane = tid & 31, wid = tid >> 5;
    int m0 = (wid & 3) * 32, n0 = (wid >> 2) * 64;

    stage_load(sbase, 0, 0, Ah, Al, Bh, Bl, bm, bn, KLD, tid);
    stage_load(sbase, 1, 1, Ah, Al, Bh, Bl, bm, bn, KLD, tid);

    uint32_t a_off = (uint32_t)(m0 + (lane & 15)) * 80 + (lane >> 4) * 16;
    uint32_t b_off = (uint32_t)(n0 + (lane & 7) + ((lane >> 4) & 1) * 8) * 80
                   + ((lane >> 3) & 1) * 16;

    for (int c = 0; c < NCHUNK; c++) {
        asm volatile("cp.async.wait_group 1;" ::: "memory");
        __syncthreads();
        int s = c % 3;
        if (c + 2 < NCHUNK)
            stage_load(sbase, (c + 2) % 3, c + 2, Ah, Al, Bh, Bl, bm, bn, KLD, tid);
        else
            asm volatile("cp.async.commit_group;" ::: "memory");

        uint32_t sb = sbase + s * STAGE_BYTES;
        #pragma unroll
        for (int ks = 0; ks < 2; ks++) {
            uint32_t ah[2][4], al[2][4], bb[8][2];
            #pragma unroll
            for (int i = 0; i < 2; i++) {
                uint32_t ad = sb + a_off + i * (16 * 80) + ks * 32;
                ldsm4(ah[i], ad);
                ldsm4(al[i], ad + 10240);
            }
            // load B-hi, run hh + lh (both consume bb)
            #pragma unroll
            for (int j2 = 0; j2 < 4; j2++) {
                uint32_t t[4];
                ldsm4(t, sb + 20480 + b_off + j2 * (16 * 80) + ks * 32);
                bb[2*j2][0] = t[0]; bb[2*j2][1] = t[1];
                bb[2*j2+1][0] = t[2]; bb[2*j2+1][1] = t[3];
            }
            #pragma unroll
            for (int i = 0; i < 2; i++)
                #pragma unroll
                for (int j = 0; j < 8; j++)
                    mma16816(acc[i][j], ah[i], bb[j]);
            #pragma unroll
            for (int i = 0; i < 2; i++)
                #pragma unroll
                for (int j = 0; j < 8; j++)
                    mma16816(acc[i][j], al[i], bb[j]);
            // overwrite bb with B-lo, run hl
            #pragma unroll
            for (int j2 = 0; j2 < 4; j2++) {
                uint32_t t[4];
                ldsm4(t, sb + 40960 + b_off + j2 * (16 * 80) + ks * 32);
                bb[2*j2][0] = t[0]; bb[2*j2][1] = t[1];
                bb[2*j2+1][0] = t[2]; bb[2*j2+1][1] = t[3];
            }
            #pragma unroll
            for (int i = 0; i < 2; i++)
                #pragma unroll
                for (int j = 0; j < 8; j++)
                    mma16816(acc[i][j], ah[i], bb[j]);
            // ll term dropped (~2^-16 relative)
        }
    }
}

// GEMM1: res = y - gx @ A^T ; writes res split bf16 hi/lo [8192,512]
__global__ __launch_bounds__(512, 1) void k_gemm1_mma(const float* __restrict__ in) {
    extern __shared__ unsigned char sm[];
    uint32_t sbase = smem_u32(sm);
    int bm = blockIdx.y * 128, bn = blockIdx.x * 256;
    float acc[2][8][4] = {};
    mma_mainloop<64, N_DIM>(sbase, g_gxh, g_gxl, g_Ah, g_Al, bm, bn, acc);

    int lane = threadIdx.x & 31, wid = threadIdx.x >> 5;
    int m0 = (wid & 3) * 32, n0 = (wid >> 2) * 64;
    #pragma unroll
    for (int i = 0; i < 2; i++) {
        int rb = bm + m0 + 16 * i + (lane >> 2);
        #pragma unroll
        for (int j = 0; j < 8; j++) {
            int col = bn + n0 + 8 * j + (lane & 3) * 2;
            #pragma unroll
            for (int h = 0; h < 2; h++) {
                int row = rb + 8 * h;
                float2 y = *(const float2*)(in + (size_t)row * IN_COLS + col);
                unsigned short h0, l0, h1, l1;
                bsplit(y.x - acc[i][j][2*h + 0], h0, l0);
                bsplit(y.y - acc[i][j][2*h + 1], h1, l1);
                size_t o = ((size_t)row * M_DIM + col) * 2;
                *(uint32_t*)(g_resh + o) = (uint32_t)h0 | ((uint32_t)h1 << 16);
                *(uint32_t*)(g_resl + o) = (uint32_t)l0 | ((uint32_t)l1 << 16);
            }
        }
    }
}

// GEMM2: zk = gx + 0.9 * res @ W ; writes zk fp32 [8192,2048]
__global__ __launch_bounds__(512, 1) void k_gemm2_mma(const float* __restrict__ in) {
    extern __shared__ unsigned char sm[];
    uint32_t sbase = smem_u32(sm);
    int bm = blockIdx.y * 128, bn = blockIdx.x * 256;
    float acc[2][8][4] = {};
    mma_mainloop<16, M_DIM>(sbase, g_resh, g_resl, g_Wth, g_Wtl, bm, bn, acc);

    int lane = threadIdx.x & 31, wid = threadIdx.x >> 5;
    int m0 = (wid & 3) * 32, n0 = (wid >> 2) * 64;
    #pragma unroll
    for (int i = 0; i < 2; i++) {
        int rb = bm + m0 + 16 * i + (lane >> 2);
        #pragma unroll
        for (int j = 0; j < 8; j++) {
            int col = bn + n0 + 8 * j + (lane & 3) * 2;
            #pragma unroll
            for (int h = 0; h < 2; h++) {
                int row = rb + 8 * h;
                float2 xk = *(const float2*)(in + (size_t)row * IN_COLS + 2560 + col);
                float gx0 = (1.0f + 0.5f * expf(-fabsf(xk.x))) * xk.x;
                float gx1 = (1.0f + 0.5f * expf(-fabsf(xk.y))) * xk.y;
                float2 z;
                z.x = gx0 + 0.9f * acc[i][j][2*h + 0];
                z.y = gx1 + 0.9f * acc[i][j][2*h + 1];
                *(float2*)(g_zk + (size_t)row * N_DIM + col) = z;
            }
        }
    }
}

// ---- shrink: 4-level histogram exact k-th largest + gating ---------------------
__global__ void k_shrink(const float* __restrict__ in, float* __restrict__ out) {
    int b = blockIdx.x, tid = threadIdx.x;
    __shared__ int hist[256];
    __shared__ unsigned s_pfx;
    __shared__ int s_k;

    const float* z = g_zk + (size_t)b * N_DIM;
    float zf[8]; unsigned vb[8];
    #pragma unroll
    for (int q = 0; q < 8; q++) {
        zf[q] = z[tid + q * 256];
        vb[q] = __float_as_uint(fabsf(zf[q]));
    }

    const int SHIFT[4] = {23, 15, 7, 0};
    const int HS[4]    = {31, 23, 15, 7};
    unsigned pfx = 0u; int k = KTH;
    #pragma unroll
    for (int lvl = 0; lvl < 4; lvl++) {
        int sh = SHIFT[lvl], hs = HS[lvl];
        hist[tid] = 0;
        __syncthreads();
        unsigned phi = pfx >> hs;
        #pragma unroll
        for (int q = 0; q < 8; q++)
            if ((vb[q] >> hs) == phi) atomicAdd(&hist[(vb[q] >> sh) & 0xFF], 1);
        __syncthreads();
        if (tid < 32) {
            int base = 255 - tid * 8, c[8], s = 0;
            #pragma unroll
            for (int j = 0; j < 8; j++) { c[j] = hist[base - j]; s += c[j]; }
            int incl = s;
            #pragma unroll
            for (int off = 1; off < 32; off <<= 1) {
                int t = __shfl_up_sync(0xffffffffu, incl, off);
                if (tid >= off) incl += t;
            }
            int excl = incl - s;
            if (excl < k && incl >= k) {
                int kk = k - excl, bin = base;
                #pragma unroll
                for (int j = 0; j < 8; j++) {
                    if (kk <= c[j]) { bin = base - j; break; }
                    kk -= c[j];
                }
                s_pfx = pfx | ((unsigned)bin << sh);
                s_k = kk;
            }
        }
        __syncthreads();
        pfx = s_pfx; k = s_k;
        __syncthreads();
    }
    float thres = __uint_as_float(pfx);

    const float* row_in = in + (size_t)b * IN_COLS;
    float* crow = out + (size_t)b * OUT_COLS + IN_COLS;
    float* orow = crow + N_DIM;
    #pragma unroll
    for (int q = 0; q < 8; q++) {
        int i = tid + q * 256;
        float zv = zf[q], az = __uint_as_float(vb[q]);
        float ind = (az > THETA && az > thres) ? 1.0f : 0.0f;
        float ci = 1.0f - ind;
        float soft = copysignf(fmaxf(az * ci - THETA, 0.0f), zv);
        float xt = ind * zv + soft;
        float xkv = row_in[2560 + i], cprv = row_in[512 + i];
        float p1 = 1.0f / (fabsf(xt - xkv) + 0.1f);
        float g = 1.0f - 0.5f * p1 * (THETA * cprv);
        crow[i] = ci;
        orow[i] = g * xt + (1.0f - g) * xkv;
    }
}

// ----------------------------------------------------------------------------------
extern "C" void kernel_launch(void* const* d_in, const int* in_sizes, int n_in,
                              void* d_out, int out_size) {
    (void)in_sizes; (void)n_in; (void)out_size;
    const float* in = (const float*)d_in[0];
    const float* A  = (const float*)d_in[1];
    const float* W  = (const float*)d_in[2];
    float* out = (float*)d_out;

    static int init = 0;
    if (!init) {
        cudaFuncSetAttribute(k_gemm1_mma, cudaFuncAttributeMaxDynamicSharedMemorySize, GEMM_SMEM);
        cudaFuncSetAttribute(k_gemm2_mma, cudaFuncAttributeMaxDynamicSharedMemorySize, GEMM_SMEM);
        init = 1;
    }

    k_copy_gx<<<B_ROWS, 256>>>(in, out);
    k_prep_A<<<M_DIM, 256>>>(A);
    k_prep_W<<<dim3(N_DIM / 32, M_DIM / 32), 256>>>(W);
    k_gemm1_mma<<<dim3(M_DIM / 256, B_ROWS / 128), 512, GEMM_SMEM>>>(in);
    k_gemm2_mma<<<dim3(N_DIM / 256, B_ROWS / 128), 512, GEMM_SMEM>>>(in);
    k_shrink<<<B_ROWS, 256>>>(in, out);
}

// round 7
// speedup vs baseline: 2.3913x; 1.0244x over previous
#include <cuda_runtime.h>
#include <cuda_bf16.h>
#include <math.h>
#include <stdint.h>

#define B_ROWS   8192
#define M_DIM    512
#define N_DIM    2048
#define IN_COLS  4608
#define OUT_COLS 8704
#define THETA    0.1f
#define KTH      103

// ---- scratch: planar bf16 hi/lo operands -----------------------------------
__device__ __align__(16) unsigned char g_gxh [33554432]; // 8192x2048 bf16
__device__ __align__(16) unsigned char g_gxl [33554432];
__device__ __align__(16) unsigned char g_Ah  [2097152];  // 512x2048
__device__ __align__(16) unsigned char g_Al  [2097152];
__device__ __align__(16) unsigned char g_Wth [2097152];  // Wt: 2048x512
__device__ __align__(16) unsigned char g_Wtl [2097152];
__device__ __align__(16) unsigned char g_resh[8388608];  // 8192x512
__device__ __align__(16) unsigned char g_resl[8388608];
__device__ float g_zk[(size_t)B_ROWS * N_DIM];

// ---- helpers ----------------------------------------------------------------
__device__ __forceinline__ uint32_t smem_u32(const void* p) {
    uint32_t a;
    asm("{ .reg .u64 t; cvta.to.shared.u64 t, %1; cvt.u32.u64 %0, t; }" : "=r"(a) : "l"(p));
    return a;
}
__device__ __forceinline__ void cpa(uint32_t dst, const void* src) {
    asm volatile("cp.async.cg.shared.global [%0], [%1], 16;" :: "r"(dst), "l"(src));
}
__device__ __forceinline__ void ldsm4(uint32_t* r, uint32_t a) {
    asm volatile("ldmatrix.sync.aligned.m8n8.x4.shared.b16 {%0,%1,%2,%3}, [%4];"
                 : "=r"(r[0]), "=r"(r[1]), "=r"(r[2]), "=r"(r[3]) : "r"(a));
}
__device__ __forceinline__ void mma16816(float* c, const uint32_t* a, const uint32_t* b) {
    asm volatile(
        "mma.sync.aligned.m16n8k16.row.col.f32.bf16.bf16.f32 "
        "{%0,%1,%2,%3}, {%4,%5,%6,%7}, {%8,%9}, {%0,%1,%2,%3};"
        : "+f"(c[0]), "+f"(c[1]), "+f"(c[2]), "+f"(c[3])
        : "r"(a[0]), "r"(a[1]), "r"(a[2]), "r"(a[3]), "r"(b[0]), "r"(b[1]));
}
union U16x8 { unsigned short s[8]; uint4 v; };
union U16x4 { unsigned short s[4]; uint2 v; };
__device__ __forceinline__ void bsplit(float x, unsigned short& h, unsigned short& l) {
    __nv_bfloat16 bh = __float2bfloat16(x);
    __nv_bfloat16 bl = __float2bfloat16(x - __bfloat162float(bh));
    h = __bfloat16_as_ushort(bh); l = __bfloat16_as_ushort(bl);
}

// ---- prep kernels -------------------------------------------------------------
// gx split only (passthrough copy moved into k_shrink)
__global__ void k_gx(const float* __restrict__ in) {
    int b = blockIdx.x, tid = threadIdx.x;
    int c0 = tid * 8;
    const float4* xs = (const float4*)(in + (size_t)b * IN_COLS + 2560 + c0);
    float4 v0 = xs[0], v1 = xs[1];
    float x[8] = {v0.x, v0.y, v0.z, v0.w, v1.x, v1.y, v1.z, v1.w};
    U16x8 ph, pl;
    #pragma unroll
    for (int e = 0; e < 8; e++) {
        float g = (1.0f + 0.5f * expf(-fabsf(x[e]))) * x[e];
        bsplit(g, ph.s[e], pl.s[e]);
    }
    size_t o = ((size_t)b * N_DIM + c0) * 2;
    *(uint4*)(g_gxh + o) = ph.v;
    *(uint4*)(g_gxl + o) = pl.v;
}

__global__ void k_prep_A(const float* __restrict__ A) {
    int n = blockIdx.x, tid = threadIdx.x, c0 = tid * 8;
    const float4* xs = (const float4*)(A + (size_t)n * N_DIM + c0);
    float4 v0 = xs[0], v1 = xs[1];
    float x[8] = {v0.x, v0.y, v0.z, v0.w, v1.x, v1.y, v1.z, v1.w};
    U16x8 ph, pl;
    #pragma unroll
    for (int e = 0; e < 8; e++) bsplit(x[e], ph.s[e], pl.s[e]);
    size_t o = ((size_t)n * N_DIM + c0) * 2;
    *(uint4*)(g_Ah + o) = ph.v;
    *(uint4*)(g_Al + o) = pl.v;
}

__global__ void k_prep_W(const float* __restrict__ W) {  // Wt[n][k] = W[k][n]
    __shared__ float ts[32][33];
    int n0 = blockIdx.x * 32, k0 = blockIdx.y * 32, tid = threadIdx.x;
    #pragma unroll
    for (int i = 0; i < 4; i++) {
        int idx = tid + i * 256, kl = idx >> 5, nl = idx & 31;
        ts[kl][nl] = W[(size_t)(k0 + kl) * N_DIM + n0 + nl];
    }
    __syncthreads();
    int nl = tid >> 3, kq = (tid & 7) * 4;
    U16x4 ph, pl;
    #pragma unroll
    for (int j = 0; j < 4; j++) bsplit(ts[kq + j][nl], ph.s[j], pl.s[j]);
    size_t o = ((size_t)(n0 + nl) * M_DIM + k0 + kq) * 2;
    *(uint2*)(g_Wth + o) = ph.v;
    *(uint2*)(g_Wtl + o) = pl.v;
}

// ---- mma.sync GEMM core ---------------------------------------------------------
// CTA tile 128x128, 256 threads (warp grid 4m x 2n, warp tile 32x64), 2 CTAs/SM.
// Stage (40960B): Ah[128][40] | Al | Bh | Bl  (80B pitch); 2 stages.
#define STAGE_BYTES 40960
#define GEMM_SMEM   (2 * STAGE_BYTES)

__device__ __forceinline__ void stage_load(
    uint32_t sbase, int s, int c,
    const unsigned char* Ah, const unsigned char* Al,
    const unsigned char* Bh, const unsigned char* Bl,
    int bm, int bn, int KLD, int tid)
{
    uint32_t sb = sbase + s * STAGE_BYTES;
    int r = tid >> 2, seg = tid & 3;
    size_t kb = ((size_t)c * 32 + seg * 8) * 2;
    #pragma unroll
    for (int p = 0; p < 2; p++) {
        int row = r + p * 64;
        size_t ga = (size_t)(bm + row) * KLD * 2 + kb;
        size_t gb = (size_t)(bn + row) * KLD * 2 + kb;
        uint32_t so = (uint32_t)row * 80 + seg * 16;
        cpa(sb + so,         Ah + ga);
        cpa(sb + 10240 + so, Al + ga);
        cpa(sb + 20480 + so, Bh + gb);
        cpa(sb + 30720 + so, Bl + gb);
    }
    asm volatile("cp.async.commit_group;" ::: "memory");
}

template<int NCHUNK, int KLD>
__device__ __forceinline__ void mma_mainloop(
    uint32_t sbase,
    const unsigned char* Ah, const unsigned char* Al,
    const unsigned char* Bh, const unsigned char* Bl,
    int bm, int bn, float acc[2][8][4])
{
    int tid = threadIdx.x, lane = tid & 31, wid = tid >> 5;
    int m0 = (wid & 3) * 32, n0 = (wid >> 2) * 64;

    stage_load(sbase, 0, 0, Ah, Al, Bh, Bl, bm, bn, KLD, tid);
    stage_load(sbase, 1, 1, Ah, Al, Bh, Bl, bm, bn, KLD, tid);

    uint32_t a_off = (uint32_t)(m0 + (lane & 15)) * 80 + (lane >> 4) * 16;
    uint32_t b_off = (uint32_t)(n0 + (lane & 7) + ((lane >> 4) & 1) * 8) * 80
                   + ((lane >> 3) & 1) * 16;

    for (int c = 0; c < NCHUNK; c++) {
        asm volatile("cp.async.wait_group 1;" ::: "memory");
        __syncthreads();
        int s = c & 1;
        uint32_t sb = sbase + s * STAGE_BYTES;
        #pragma unroll
        for (int ks = 0; ks < 2; ks++) {
            uint32_t ah[2][4], al[2][4], bb[8][2];
            #pragma unroll
            for (int i = 0; i < 2; i++) {
                uint32_t ad = sb + a_off + i * (16 * 80) + ks * 32;
                ldsm4(ah[i], ad);
                ldsm4(al[i], ad + 10240);
            }
            #pragma unroll
            for (int j2 = 0; j2 < 4; j2++) {
                uint32_t t[4];
                ldsm4(t, sb + 20480 + b_off + j2 * (16 * 80) + ks * 32);
                bb[2*j2][0] = t[0]; bb[2*j2][1] = t[1];
                bb[2*j2+1][0] = t[2]; bb[2*j2+1][1] = t[3];
            }
            #pragma unroll
            for (int i = 0; i < 2; i++)
                #pragma unroll
                for (int j = 0; j < 8; j++)
                    mma16816(acc[i][j], ah[i], bb[j]);
            #pragma unroll
            for (int i = 0; i < 2; i++)
                #pragma unroll
                for (int j = 0; j < 8; j++)
                    mma16816(acc[i][j], al[i], bb[j]);
            #pragma unroll
            for (int j2 = 0; j2 < 4; j2++) {
                uint32_t t[4];
                ldsm4(t, sb + 30720 + b_off + j2 * (16 * 80) + ks * 32);
                bb[2*j2][0] = t[0]; bb[2*j2][1] = t[1];
                bb[2*j2+1][0] = t[2]; bb[2*j2+1][1] = t[3];
            }
            #pragma unroll
            for (int i = 0; i < 2; i++)
                #pragma unroll
                for (int j = 0; j < 8; j++)
                    mma16816(acc[i][j], ah[i], bb[j]);
            // ll term dropped (~2^-16 relative)
        }
        __syncthreads();   // buffer s fully consumed; safe to refill
        if (c + 2 < NCHUNK)
            stage_load(sbase, s, c + 2, Ah, Al, Bh, Bl, bm, bn, KLD, tid);
        else
            asm volatile("cp.async.commit_group;" ::: "memory");
    }
}

// GEMM1: res = y - gx @ A^T ; writes res split bf16 hi/lo [8192,512]
__global__ __launch_bounds__(256, 2) void k_gemm1_mma(const float* __restrict__ in) {
    extern __shared__ unsigned char sm[];
    uint32_t sbase = smem_u32(sm);
    int bm = blockIdx.y * 128, bn = blockIdx.x * 128;
    float acc[2][8][4] = {};
    mma_mainloop<64, N_DIM>(sbase, g_gxh, g_gxl, g_Ah, g_Al, bm, bn, acc);

    int lane = threadIdx.x & 31, wid = threadIdx.x >> 5;
    int m0 = (wid & 3) * 32, n0 = (wid >> 2) * 64;
    #pragma unroll
    for (int i = 0; i < 2; i++) {
        int rb = bm + m0 + 16 * i + (lane >> 2);
        #pragma unroll
        for (int j = 0; j < 8; j++) {
            int col = bn + n0 + 8 * j + (lane & 3) * 2;
            #pragma unroll
            for (int h = 0; h < 2; h++) {
                int row = rb + 8 * h;
                float2 y = *(const float2*)(in + (size_t)row * IN_COLS + col);
                unsigned short h0, l0, h1, l1;
                bsplit(y.x - acc[i][j][2*h + 0], h0, l0);
                bsplit(y.y - acc[i][j][2*h + 1], h1, l1);
                size_t o = ((size_t)row * M_DIM + col) * 2;
                *(uint32_t*)(g_resh + o) = (uint32_t)h0 | ((uint32_t)h1 << 16);
                *(uint32_t*)(g_resl + o) = (uint32_t)l0 | ((uint32_t)l1 << 16);
            }
        }
    }
}

// GEMM2: zk = gx + 0.9 * res @ W ; writes zk fp32 [8192,2048]
__global__ __launch_bounds__(256, 2) void k_gemm2_mma(const float* __restrict__ in) {
    extern __shared__ unsigned char sm[];
    uint32_t sbase = smem_u32(sm);
    int bm = blockIdx.y * 128, bn = blockIdx.x * 128;
    float acc[2][8][4] = {};
    mma_mainloop<16, M_DIM>(sbase, g_resh, g_resl, g_Wth, g_Wtl, bm, bn, acc);

    int lane = threadIdx.x & 31, wid = threadIdx.x >> 5;
    int m0 = (wid & 3) * 32, n0 = (wid >> 2) * 64;
    #pragma unroll
    for (int i = 0; i < 2; i++) {
        int rb = bm + m0 + 16 * i + (lane >> 2);
        #pragma unroll
        for (int j = 0; j < 8; j++) {
            int col = bn + n0 + 8 * j + (lane & 3) * 2;
            #pragma unroll
            for (int h = 0; h < 2; h++) {
                int row = rb + 8 * h;
                float2 xk = *(const float2*)(in + (size_t)row * IN_COLS + 2560 + col);
                float gx0 = (1.0f + 0.5f * expf(-fabsf(xk.x))) * xk.x;
                float gx1 = (1.0f + 0.5f * expf(-fabsf(xk.y))) * xk.y;
                float2 z;
                z.x = gx0 + 0.9f * acc[i][j][2*h + 0];
                z.y = gx1 + 0.9f * acc[i][j][2*h + 1];
                *(float2*)(g_zk + (size_t)row * N_DIM + col) = z;
            }
        }
    }
}

// ---- shrink: histogram k-th largest + gating + fused input passthrough ---------
__global__ void k_shrink(const float* __restrict__ in, float* __restrict__ out) {
    int b = blockIdx.x, tid = threadIdx.x;
    __shared__ int hist[256];
    __shared__ unsigned s_pfx;
    __shared__ int s_k;

    const float* z = g_zk + (size_t)b * N_DIM;
    float zf[8]; unsigned vb[8];
    #pragma unroll
    for (int q = 0; q < 8; q++) {
        zf[q] = z[tid + q * 256];
        vb[q] = __float_as_uint(fabsf(zf[q]));
    }

    const int SHIFT[4] = {23, 15, 7, 0};
    const int HS[4]    = {31, 23, 15, 7};
    unsigned pfx = 0u; int k = KTH;
    #pragma unroll
    for (int lvl = 0; lvl < 4; lvl++) {
        int sh = SHIFT[lvl], hs = HS[lvl];
        hist[tid] = 0;
        __syncthreads();
        unsigned phi = pfx >> hs;
        #pragma unroll
        for (int q = 0; q < 8; q++)
            if ((vb[q] >> hs) == phi) atomicAdd(&hist[(vb[q] >> sh) & 0xFF], 1);
        __syncthreads();
        if (tid < 32) {
            int base = 255 - tid * 8, c[8], s = 0;
            #pragma unroll
            for (int j = 0; j < 8; j++) { c[j] = hist[base - j]; s += c[j]; }
            int incl = s;
            #pragma unroll
            for (int off = 1; off < 32; off <<= 1) {
                int t = __shfl_up_sync(0xffffffffu, incl, off);
                if (tid >= off) incl += t;
            }
            int excl = incl - s;
            if (excl < k && incl >= k) {
                int kk = k - excl, bin = base;
                #pragma unroll
                for (int j = 0; j < 8; j++) {
                    if (kk <= c[j]) { bin = base - j; break; }
                    kk -= c[j];
                }
                s_pfx = pfx | ((unsigned)bin << sh);
                s_k = kk;
            }
        }
        __syncthreads();
        pfx = s_pfx; k = s_k;
        __syncthreads();
    }
    float thres = __uint_as_float(pfx);

    const float* row_in = in + (size_t)b * IN_COLS;
    float* crow = out + (size_t)b * OUT_COLS + IN_COLS;
    float* orow = crow + N_DIM;
    #pragma unroll
    for (int q = 0; q < 8; q++) {
        int i = tid + q * 256;
        float zv = zf[q], az = __uint_as_float(vb[q]);
        float ind = (az > THETA && az > thres) ? 1.0f : 0.0f;
        float ci = 1.0f - ind;
        float soft = copysignf(fmaxf(az * ci - THETA, 0.0f), zv);
        float xt = ind * zv + soft;
        float xkv = row_in[2560 + i], cprv = row_in[512 + i];
        float p1 = 1.0f / (fabsf(xt - xkv) + 0.1f);
        float g = 1.0f - 0.5f * p1 * (THETA * cprv);
        crow[i] = ci;
        orow[i] = g * xt + (1.0f - g) * xkv;
    }

    // fused passthrough: out[:, :4608] = in
    const float4* src = (const float4*)row_in;
    float4* dst = (float4*)(out + (size_t)b * OUT_COLS);
    #pragma unroll 2
    for (int i = tid; i < IN_COLS / 4; i += 256) dst[i] = src[i];
}

// ----------------------------------------------------------------------------------
extern "C" void kernel_launch(void* const* d_in, const int* in_sizes, int n_in,
                              void* d_out, int out_size) {
    (void)in_sizes; (void)n_in; (void)out_size;
    const float* in = (const float*)d_in[0];
    const float* A  = (const float*)d_in[1];
    const float* W  = (const float*)d_in[2];
    float* out = (float*)d_out;

    static int init = 0;
    if (!init) {
        cudaFuncSetAttribute(k_gemm1_mma, cudaFuncAttributeMaxDynamicSharedMemorySize, GEMM_SMEM);
        cudaFuncSetAttribute(k_gemm2_mma, cudaFuncAttributeMaxDynamicSharedMemorySize, GEMM_SMEM);
        init = 1;
    }

    k_gx<<<B_ROWS, 256>>>(in);
    k_prep_A<<<M_DIM, 256>>>(A);
    k_prep_W<<<dim3(N_DIM / 32, M_DIM / 32), 256>>>(W);
    k_gemm1_mma<<<dim3(M_DIM / 128, B_ROWS / 128), 256, GEMM_SMEM>>>(in);
    k_gemm2_mma<<<dim3(N_DIM / 128, B_ROWS / 128), 256, GEMM_SMEM>>>(in);
    k_shrink<<<B_ROWS, 256>>>(in, out);
}

// round 9
// speedup vs baseline: 2.5723x; 1.0757x over previous
#include <cuda_runtime.h>
#include <cuda_bf16.h>
#include <math.h>
#include <stdint.h>

#define B_ROWS   8192
#define M_DIM    512
#define N_DIM    2048
#define IN_COLS  4608
#define OUT_COLS 8704
#define THETA    0.1f
#define KTH      103

// ---- scratch: planar bf16 hi/lo operands -----------------------------------
__device__ __align__(16) unsigned char g_gxh [33554432]; // 8192x2048 bf16
__device__ __align__(16) unsigned char g_gxl [33554432];
__device__ __align__(16) unsigned char g_Ah  [2097152];  // 512x2048
__device__ __align__(16) unsigned char g_Al  [2097152];
__device__ __align__(16) unsigned char g_Wth [2097152];  // Wt: 2048x512
__device__ __align__(16) unsigned char g_Wtl [2097152];
__device__ __align__(16) unsigned char g_resh[8388608];  // 8192x512
__device__ __align__(16) unsigned char g_resl[8388608];
__device__ float g_zk[(size_t)B_ROWS * N_DIM];

// ---- helpers ----------------------------------------------------------------
__device__ __forceinline__ uint32_t smem_u32(const void* p) {
    uint32_t a;
    asm("{ .reg .u64 t; cvta.to.shared.u64 t, %1; cvt.u32.u64 %0, t; }" : "=r"(a) : "l"(p));
    return a;
}
__device__ __forceinline__ void cpa(uint32_t dst, const void* src) {
    asm volatile("cp.async.cg.shared.global [%0], [%1], 16;" :: "r"(dst), "l"(src));
}
__device__ __forceinline__ void ldsm4(uint32_t* r, uint32_t a) {
    asm volatile("ldmatrix.sync.aligned.m8n8.x4.shared.b16 {%0,%1,%2,%3}, [%4];"
                 : "=r"(r[0]), "=r"(r[1]), "=r"(r[2]), "=r"(r[3]) : "r"(a));
}
__device__ __forceinline__ void mma16816(float* c, const uint32_t* a, const uint32_t* b) {
    asm volatile(
        "mma.sync.aligned.m16n8k16.row.col.f32.bf16.bf16.f32 "
        "{%0,%1,%2,%3}, {%4,%5,%6,%7}, {%8,%9}, {%0,%1,%2,%3};"
        : "+f"(c[0]), "+f"(c[1]), "+f"(c[2]), "+f"(c[3])
        : "r"(a[0]), "r"(a[1]), "r"(a[2]), "r"(a[3]), "r"(b[0]), "r"(b[1]));
}
union U16x8 { unsigned short s[8]; uint4 v; };
union U16x4 { unsigned short s[4]; uint2 v; };
__device__ __forceinline__ void bsplit(float x, unsigned short& h, unsigned short& l) {
    __nv_bfloat16 bh = __float2bfloat16(x);
    __nv_bfloat16 bl = __float2bfloat16(x - __bfloat162float(bh));
    h = __bfloat16_as_ushort(bh); l = __bfloat16_as_ushort(bl);
}

// ---- prep kernels -------------------------------------------------------------
__global__ void k_gx(const float* __restrict__ in) {
    int b = blockIdx.x, tid = threadIdx.x;
    int c0 = tid * 8;
    const float4* xs = (const float4*)(in + (size_t)b * IN_COLS + 2560 + c0);
    float4 v0 = xs[0], v1 = xs[1];
    float x[8] = {v0.x, v0.y, v0.z, v0.w, v1.x, v1.y, v1.z, v1.w};
    U16x8 ph, pl;
    #pragma unroll
    for (int e = 0; e < 8; e++) {
        float g = (1.0f + 0.5f * expf(-fabsf(x[e]))) * x[e];
        bsplit(g, ph.s[e], pl.s[e]);
    }
    size_t o = ((size_t)b * N_DIM + c0) * 2;
    *(uint4*)(g_gxh + o) = ph.v;
    *(uint4*)(g_gxl + o) = pl.v;
}

__global__ void k_prep_A(const float* __restrict__ A) {
    int n = blockIdx.x, tid = threadIdx.x, c0 = tid * 8;
    const float4* xs = (const float4*)(A + (size_t)n * N_DIM + c0);
    float4 v0 = xs[0], v1 = xs[1];
    float x[8] = {v0.x, v0.y, v0.z, v0.w, v1.x, v1.y, v1.z, v1.w};
    U16x8 ph, pl;
    #pragma unroll
    for (int e = 0; e < 8; e++) bsplit(x[e], ph.s[e], pl.s[e]);
    size_t o = ((size_t)n * N_DIM + c0) * 2;
    *(uint4*)(g_Ah + o) = ph.v;
    *(uint4*)(g_Al + o) = pl.v;
}

__global__ void k_prep_W(const float* __restrict__ W) {  // Wt[n][k] = W[k][n]
    __shared__ float ts[32][33];
    int n0 = blockIdx.x * 32, k0 = blockIdx.y * 32, tid = threadIdx.x;
    #pragma unroll
    for (int i = 0; i < 4; i++) {
        int idx = tid + i * 256, kl = idx >> 5, nl = idx & 31;
        ts[kl][nl] = W[(size_t)(k0 + kl) * N_DIM + n0 + nl];
    }
    __syncthreads();
    int nl = tid >> 3, kq = (tid & 7) * 4;
    U16x4 ph, pl;
    #pragma unroll
    for (int j = 0; j < 4; j++) bsplit(ts[kq + j][nl], ph.s[j], pl.s[j]);
    size_t o = ((size_t)(n0 + nl) * M_DIM + k0 + kq) * 2;
    *(uint2*)(g_Wth + o) = ph.v;
    *(uint2*)(g_Wtl + o) = pl.v;
}

// ---- mma.sync GEMM core ---------------------------------------------------------
// CTA tile 128x128, 256 threads (warp grid 4m x 2n, warp tile 32x64), 1 CTA/SM.
// 3 stages x 40960B: Ah[128][40] | Al | Bh | Bl (80B pitch).
// Register-level fragment double buffering: MMA operands always one block ahead.
#define STAGE_BYTES 40960
#define GEMM_SMEM   (3 * STAGE_BYTES)

struct Frags { uint32_t ah[2][4]; uint32_t al[2][4]; uint32_t bh[8][2]; uint32_t bl[8][2]; };

__device__ __forceinline__ void frag_load(Frags& f, uint32_t sb, uint32_t a_off,
                                          uint32_t b_off, int ks) {
    #pragma unroll
    for (int i = 0; i < 2; i++) {
        uint32_t ad = sb + a_off + i * (16 * 80) + ks * 32;
        ldsm4(f.ah[i], ad);
        ldsm4(f.al[i], ad + 10240);
    }
    #pragma unroll
    for (int j2 = 0; j2 < 4; j2++) {
        uint32_t bd = sb + 20480 + b_off + j2 * (16 * 80) + ks * 32;
        uint32_t t[4];
        ldsm4(t, bd);
        f.bh[2*j2][0] = t[0]; f.bh[2*j2][1] = t[1];
        f.bh[2*j2+1][0] = t[2]; f.bh[2*j2+1][1] = t[3];
        ldsm4(t, bd + 10240);
        f.bl[2*j2][0] = t[0]; f.bl[2*j2][1] = t[1];
        f.bl[2*j2+1][0] = t[2]; f.bl[2*j2+1][1] = t[3];
    }
}

__device__ __forceinline__ void mma_block(float acc[2][8][4], const Frags& f) {
    #pragma unroll
    for (int i = 0; i < 2; i++)
        #pragma unroll
        for (int j = 0; j < 8; j++)
            mma16816(acc[i][j], f.ah[i], f.bh[j]);
    #pragma unroll
    for (int i = 0; i < 2; i++)
        #pragma unroll
        for (int j = 0; j < 8; j++)
            mma16816(acc[i][j], f.al[i], f.bh[j]);
    #pragma unroll
    for (int i = 0; i < 2; i++)
        #pragma unroll
        for (int j = 0; j < 8; j++)
            mma16816(acc[i][j], f.ah[i], f.bl[j]);
    // ll term dropped (~2^-16 relative)
}

__device__ __forceinline__ void stage_load(
    uint32_t sbase, int s, int c,
    const unsigned char* Ah, const unsigned char* Al,
    const unsigned char* Bh, const unsigned char* Bl,
    int bm, int bn, int KLD, int tid)
{
    uint32_t sb = sbase + s * STAGE_BYTES;
    int r = tid >> 2, seg = tid & 3;
    size_t kb = ((size_t)c * 32 + seg * 8) * 2;
    #pragma unroll
    for (int p = 0; p < 2; p++) {
        int row = r + p * 64;
        size_t ga = (size_t)(bm + row) * KLD * 2 + kb;
        size_t gb = (size_t)(bn + row) * KLD * 2 + kb;
        uint32_t so = (uint32_t)row * 80 + seg * 16;
        cpa(sb + so,         Ah + ga);
        cpa(sb + 10240 + so, Al + ga);
        cpa(sb + 20480 + so, Bh + gb);
        cpa(sb + 30720 + so, Bl + gb);
    }
    asm volatile("cp.async.commit_group;" ::: "memory");
}

template<int NCHUNK, int KLD>
__device__ __forceinline__ void mma_mainloop(
    uint32_t sbase,
    const unsigned char* Ah, const unsigned char* Al,
    const unsigned char* Bh, const unsigned char* Bl,
    int bm, int bn, float acc[2][8][4])
{
    int tid = threadIdx.x, lane = tid & 31, wid = tid >> 5;
    int m0 = (wid & 3) * 32, n0 = (wid >> 2) * 64;

    stage_load(sbase, 0, 0, Ah, Al, Bh, Bl, bm, bn, KLD, tid);
    stage_load(sbase, 1, 1, Ah, Al, Bh, Bl, bm, bn, KLD, tid);
    stage_load(sbase, 2, 2, Ah, Al, Bh, Bl, bm, bn, KLD, tid);

    uint32_t a_off = (uint32_t)(m0 + (lane & 15)) * 80 + (lane >> 4) * 16;
    uint32_t b_off = (uint32_t)(n0 + (lane & 7) + ((lane >> 4) & 1) * 8) * 80
                   + ((lane >> 3) & 1) * 16;

    asm volatile("cp.async.wait_group 2;" ::: "memory");
    __syncthreads();

    Frags fr[2];
    frag_load(fr[0], sbase, a_off, b_off, 0);   // chunk 0, ks 0

    for (int c = 0; c < NCHUNK; c++) {
        int s = c % 3;
        uint32_t sb = sbase + s * STAGE_BYTES;
        // --- ks = 0: prefetch ks1 frags (last read of stage s), then MMA ks0
        frag_load(fr[1], sb, a_off, b_off, 1);
        mma_block(acc, fr[0]);
        // barrier hidden under the ks0 MMA queue; also publishes stage c+1
        asm volatile("cp.async.wait_group 1;" ::: "memory");
        __syncthreads();
        // refill stage s with chunk c+3 (all readers of s are done)
        if (c + 3 < NCHUNK)
            stage_load(sbase, s, c + 3, Ah, Al, Bh, Bl, bm, bn, KLD, tid);
        else
            asm volatile("cp.async.commit_group;" ::: "memory");
        // --- ks = 1: prefetch next chunk ks0 frags from stage c+1, then MMA ks1
        frag_load(fr[0], sbase + ((c + 1) % 3) * STAGE_BYTES, a_off, b_off, 0);
        mma_block(acc, fr[1]);
    }
}

// GEMM1: res = y - gx @ A^T ; writes res split bf16 hi/lo [8192,512]
__global__ __launch_bounds__(256, 1) void k_gemm1_mma(const float* __restrict__ in) {
    extern __shared__ unsigned char sm[];
    uint32_t sbase = smem_u32(sm);
    int bm = blockIdx.y * 128, bn = blockIdx.x * 128;
    float acc[2][8][4] = {};
    mma_mainloop<64, N_DIM>(sbase, g_gxh, g_gxl, g_Ah, g_Al, bm, bn, acc);

    int lane = threadIdx.x & 31, wid = threadIdx.x >> 5;
    int m0 = (wid & 3) * 32, n0 = (wid >> 2) * 64;
    #pragma unroll
    for (int i = 0; i < 2; i++) {
        int rb = bm + m0 + 16 * i + (lane >> 2);
        #pragma unroll
        for (int j = 0; j < 8; j++) {
            int col = bn + n0 + 8 * j + (lane & 3) * 2;
            #pragma unroll
            for (int h = 0; h < 2; h++) {
                int row = rb + 8 * h;
                float2 y = *(const float2*)(in + (size_t)row * IN_COLS + col);
                unsigned short h0, l0, h1, l1;
                bsplit(y.x - acc[i][j][2*h + 0], h0, l0);
                bsplit(y.y - acc[i][j][2*h + 1], h1, l1);
                size_t o = ((size_t)row * M_DIM + col) * 2;
                *(uint32_t*)(g_resh + o) = (uint32_t)h0 | ((uint32_t)h1 << 16);
                *(uint32_t*)(g_resl + o) = (uint32_t)l0 | ((uint32_t)l1 << 16);
            }
        }
    }
}

// GEMM2: zk = gx + 0.9 * res @ W ; writes zk fp32 [8192,2048]
__global__ __launch_bounds__(256, 1) void k_gemm2_mma(const float* __restrict__ in) {
    extern __shared__ unsigned char sm[];
    uint32_t sbase = smem_u32(sm);
    int bm = blockIdx.y * 128, bn = blockIdx.x * 128;
    float acc[2][8][4] = {};
    mma_mainloop<16, M_DIM>(sbase, g_resh, g_resl, g_Wth, g_Wtl, bm, bn, acc);

    int lane = threadIdx.x & 31, wid = threadIdx.x >> 5;
    int m0 = (wid & 3) * 32, n0 = (wid >> 2) * 64;
    #pragma unroll
    for (int i = 0; i < 2; i++) {
        int rb = bm + m0 + 16 * i + (lane >> 2);
        #pragma unroll
        for (int j = 0; j < 8; j++) {
            int col = bn + n0 + 8 * j + (lane & 3) * 2;
            #pragma unroll
            for (int h = 0; h < 2; h++) {
                int row = rb + 8 * h;
                float2 xk = *(const float2*)(in + (size_t)row * IN_COLS + 2560 + col);
                float gx0 = (1.0f + 0.5f * expf(-fabsf(xk.x))) * xk.x;
                float gx1 = (1.0f + 0.5f * expf(-fabsf(xk.y))) * xk.y;
                float2 z;
                z.x = gx0 + 0.9f * acc[i][j][2*h + 0];
                z.y = gx1 + 0.9f * acc[i][j][2*h + 1];
                *(float2*)(g_zk + (size_t)row * N_DIM + col) = z;
            }
        }
    }
}

// ---- shrink: histogram k-th largest + gating + fused input passthrough ---------
__global__ void k_shrink(const float* __restrict__ in, float* __restrict__ out) {
    int b = blockIdx.x, tid = threadIdx.x;
    __shared__ int hist[256];
    __shared__ unsigned s_pfx;
    __shared__ int s_k;

    const float* z = g_zk + (size_t)b * N_DIM;
    float zf[8]; unsigned vb[8];
    #pragma unroll
    for (int q = 0; q < 8; q++) {
        zf[q] = z[tid + q * 256];
        vb[q] = __float_as_uint(fabsf(zf[q]));
    }

    const int SHIFT[4] = {23, 15, 7, 0};
    const int HS[4]    = {31, 23, 15, 7};
    unsigned pfx = 0u; int k = KTH;
    #pragma unroll
    for (int lvl = 0; lvl < 4; lvl++) {
        int sh = SHIFT[lvl], hs = HS[lvl];
        hist[tid] = 0;
        __syncthreads();
        unsigned phi = pfx >> hs;
        #pragma unroll
        for (int q = 0; q < 8; q++)
            if ((vb[q] >> hs) == phi) atomicAdd(&hist[(vb[q] >> sh) & 0xFF], 1);
        __syncthreads();
        if (tid < 32) {
            int base = 255 - tid * 8, c[8], s = 0;
            #pragma unroll
            for (int j = 0; j < 8; j++) { c[j] = hist[base - j]; s += c[j]; }
            int incl = s;
            #pragma unroll
            for (int off = 1; off < 32; off <<= 1) {
                int t = __shfl_up_sync(0xffffffffu, incl, off);
                if (tid >= off) incl += t;
            }
            int excl = incl - s;
            if (excl < k && incl >= k) {
                int kk = k - excl, bin = base;
                #pragma unroll
                for (int j = 0; j < 8; j++) {
                    if (kk <= c[j]) { bin = base - j; break; }
                    kk -= c[j];
                }
                s_pfx = pfx | ((unsigned)bin << sh);
                s_k = kk;
            }
        }
        __syncthreads();
        pfx = s_pfx; k = s_k;
        __syncthreads();
    }
    float thres = __uint_as_float(pfx);

    const float* row_in = in + (size_t)b * IN_COLS;
    float* crow = out + (size_t)b * OUT_COLS + IN_COLS;
    float* orow = crow + N_DIM;
    #pragma unroll
    for (int q = 0; q < 8; q++) {
        int i = tid + q * 256;
        float zv = zf[q], az = __uint_as_float(vb[q]);
        float ind = (az > THETA && az > thres) ? 1.0f : 0.0f;
        float ci = 1.0f - ind;
        float soft = copysignf(fmaxf(az * ci - THETA, 0.0f), zv);
        float xt = ind * zv + soft;
        float xkv = row_in[2560 + i], cprv = row_in[512 + i];
        float p1 = 1.0f / (fabsf(xt - xkv) + 0.1f);
        float g = 1.0f - 0.5f * p1 * (THETA * cprv);
        crow[i] = ci;
        orow[i] = g * xt + (1.0f - g) * xkv;
    }

    // fused passthrough: out[:, :4608] = in
    const float4* src = (const float4*)row_in;
    float4* dst = (float4*)(out + (size_t)b * OUT_COLS);
    #pragma unroll 2
    for (int i = tid; i < IN_COLS / 4; i += 256) dst[i] = src[i];
}

// ----------------------------------------------------------------------------------
extern "C" void kernel_launch(void* const* d_in, const int* in_sizes, int n_in,
                              void* d_out, int out_size) {
    (void)in_sizes; (void)n_in; (void)out_size;
    const float* in = (const float*)d_in[0];
    const float* A  = (const float*)d_in[1];
    const float* W  = (const float*)d_in[2];
    float* out = (float*)d_out;

    static int init = 0;
    if (!init) {
        cudaFuncSetAttribute(k_gemm1_mma, cudaFuncAttributeMaxDynamicSharedMemorySize, GEMM_SMEM);
        cudaFuncSetAttribute(k_gemm2_mma, cudaFuncAttributeMaxDynamicSharedMemorySize, GEMM_SMEM);
        init = 1;
    }

    k_gx<<<B_ROWS, 256>>>(in);
    k_prep_A<<<M_DIM, 256>>>(A);
    k_prep_W<<<dim3(N_DIM / 32, M_DIM / 32), 256>>>(W);
    k_gemm1_mma<<<dim3(M_DIM / 128, B_ROWS / 128), 256, GEMM_SMEM>>>(in);
    k_gemm2_mma<<<dim3(N_DIM / 128, B_ROWS / 128), 256, GEMM_SMEM>>>(in);
    k_shrink<<<B_ROWS, 256>>>(in, out);
}